// round 1
// baseline (speedup 1.0000x reference)
#include <cuda_runtime.h>
#include <math.h>

#define TB 2
#define TT 2048
#define TC 1024
#define TH 16
#define HD 64
#define BT (TB*TT)   // 4096 rows total

// Scratch (allocation-free): qkv = [BT, 3C], y = [BT, C]
__device__ float g_qkv[(size_t)BT * 3 * TC];
__device__ float g_y[(size_t)BT * TC];

// ---------------------------------------------------------------------------
// Tiled SGEMM: C[M,N] = A[M,K] @ B[K,N], row-major. M,N multiples of 64,
// K multiple of 16. Block = 256 threads, 64x64 tile, 4x4 per-thread microtile.
// ---------------------------------------------------------------------------
__global__ __launch_bounds__(256) void sgemm64(const float* __restrict__ A,
                                               const float* __restrict__ B,
                                               float* __restrict__ C,
                                               int M, int N, int K) {
    __shared__ float As[16][68];   // pitch 68: keeps float4 reads aligned, low conflict
    __shared__ float Bs[16][64];

    const int tid = threadIdx.x;
    const int tx = tid & 15;       // 0..15 -> n direction
    const int ty = tid >> 4;       // 0..15 -> m direction
    const int m0 = blockIdx.y * 64;
    const int n0 = blockIdx.x * 64;

    // load mapping: A tile 64x16 as float4 along k, B tile 16x64 as float4 along n
    const int am = tid >> 2;            // 0..63
    const int ak = (tid & 3) * 4;       // 0,4,8,12
    const int bk = tid >> 4;            // 0..15
    const int bn = (tid & 15) * 4;      // 0..60

    float acc[4][4];
#pragma unroll
    for (int i = 0; i < 4; i++)
#pragma unroll
        for (int j = 0; j < 4; j++) acc[i][j] = 0.f;

    for (int k0 = 0; k0 < K; k0 += 16) {
        const float4 av = *(const float4*)&A[(size_t)(m0 + am) * K + k0 + ak];
        const float4 bv = *(const float4*)&B[(size_t)(k0 + bk) * N + n0 + bn];
        As[ak + 0][am] = av.x;
        As[ak + 1][am] = av.y;
        As[ak + 2][am] = av.z;
        As[ak + 3][am] = av.w;
        *(float4*)&Bs[bk][bn] = bv;
        __syncthreads();

#pragma unroll
        for (int kk = 0; kk < 16; ++kk) {
            const float4 a4 = *(const float4*)&As[kk][ty * 4];
            const float4 b4 = *(const float4*)&Bs[kk][tx * 4];
            const float a[4] = {a4.x, a4.y, a4.z, a4.w};
            const float b[4] = {b4.x, b4.y, b4.z, b4.w};
#pragma unroll
            for (int i = 0; i < 4; i++)
#pragma unroll
                for (int j = 0; j < 4; j++) acc[i][j] += a[i] * b[j];
        }
        __syncthreads();
    }

#pragma unroll
    for (int i = 0; i < 4; i++) {
        float4 cv = make_float4(acc[i][0], acc[i][1], acc[i][2], acc[i][3]);
        *(float4*)&C[(size_t)(m0 + ty * 4 + i) * N + n0 + tx * 4] = cv;
    }
}

// ---------------------------------------------------------------------------
// Flash-style causal attention, fp32. One block = 64 query rows of one (b,h).
// 256 threads (16x16): thread (ty,tx) owns rows ty*4+i and cols/dcols tx*4+j.
// Online softmax; smem tiles with pitch 65 (conflict-free-ish scalar LDS).
// ---------------------------------------------------------------------------
__global__ __launch_bounds__(256) void attn64(const float* __restrict__ qkv,
                                              float* __restrict__ y) {
    extern __shared__ float sm[];
    float* Qs = sm;                 // [64][65]
    float* Ks = Qs + 64 * 65;       // [64][65]
    float* Vs = Ks + 64 * 65;       // [64][65]
    float* Ps = Vs + 64 * 65;       // [64][65]

    const int qb = blockIdx.x;       // q-tile index, 0..31
    const int h  = blockIdx.y;
    const int b  = blockIdx.z;
    const int q0 = qb * 64;
    const int tid = threadIdx.x;
    const int tx = tid & 15;
    const int ty = tid >> 4;

    const size_t rowstride = 3 * TC;
    const float* base = qkv + (size_t)b * TT * rowstride + h * HD;

    // Load Q tile (coalesced along d)
    for (int i = tid; i < 64 * 64; i += 256) {
        const int r = i >> 6, d = i & 63;
        Qs[r * 65 + d] = base[(size_t)(q0 + r) * rowstride + d];
    }

    float m[4], l[4], o[4][4];
#pragma unroll
    for (int i = 0; i < 4; i++) {
        m[i] = -1e30f;
        l[i] = 0.f;
#pragma unroll
        for (int j = 0; j < 4; j++) o[i][j] = 0.f;
    }

    for (int kt = 0; kt <= qb; ++kt) {
        const int k0 = kt * 64;
        __syncthreads();   // previous PV reads of Ks/Vs/Ps complete
        for (int i = tid; i < 64 * 64; i += 256) {
            const int r = i >> 6, d = i & 63;
            const float* p = base + (size_t)(k0 + r) * rowstride + d;
            Ks[r * 65 + d] = p[TC];        // K
            Vs[r * 65 + d] = p[2 * TC];    // V
        }
        __syncthreads();

        // S = Q @ K^T (thread holds 4x4 of the 64x64 score tile)
        float s[4][4];
#pragma unroll
        for (int i = 0; i < 4; i++)
#pragma unroll
            for (int j = 0; j < 4; j++) s[i][j] = 0.f;

#pragma unroll 4
        for (int d = 0; d < 64; ++d) {
            float a[4], bb[4];
#pragma unroll
            for (int i = 0; i < 4; i++) a[i] = Qs[(ty * 4 + i) * 65 + d];
#pragma unroll
            for (int j = 0; j < 4; j++) bb[j] = Ks[(tx * 4 + j) * 65 + d];
#pragma unroll
            for (int i = 0; i < 4; i++)
#pragma unroll
                for (int j = 0; j < 4; j++) s[i][j] += a[i] * bb[j];
        }

        const bool diag = (kt == qb);
#pragma unroll
        for (int i = 0; i < 4; i++) {
            const int r = ty * 4 + i;
            float sv[4];
#pragma unroll
            for (int j = 0; j < 4; j++) {
                float v = s[i][j] * 0.125f;   // 1/sqrt(64)
                if (diag && (tx * 4 + j) > r) v = -1e30f;
                sv[j] = v;
            }
            // row max across the 16 threads (lanes xor 1,2,4,8 stay in 16-group)
            float mloc = fmaxf(fmaxf(sv[0], sv[1]), fmaxf(sv[2], sv[3]));
#pragma unroll
            for (int off = 8; off >= 1; off >>= 1)
                mloc = fmaxf(mloc, __shfl_xor_sync(0xffffffffu, mloc, off));
            const float mnew = fmaxf(m[i], mloc);

            float p[4], rs = 0.f;
#pragma unroll
            for (int j = 0; j < 4; j++) {
                p[j] = __expf(sv[j] - mnew);
                rs += p[j];
            }
#pragma unroll
            for (int off = 8; off >= 1; off >>= 1)
                rs += __shfl_xor_sync(0xffffffffu, rs, off);

            const float f = __expf(m[i] - mnew);
            l[i] = l[i] * f + rs;
            m[i] = mnew;
#pragma unroll
            for (int j = 0; j < 4; j++) o[i][j] *= f;
#pragma unroll
            for (int j = 0; j < 4; j++) Ps[r * 65 + tx * 4 + j] = p[j];
        }
        __syncthreads();

        // O += P @ V
#pragma unroll 4
        for (int kc = 0; kc < 64; ++kc) {
            float pp[4], vv[4];
#pragma unroll
            for (int i = 0; i < 4; i++) pp[i] = Ps[(ty * 4 + i) * 65 + kc];
#pragma unroll
            for (int j = 0; j < 4; j++) vv[j] = Vs[kc * 65 + tx * 4 + j];
#pragma unroll
            for (int i = 0; i < 4; i++)
#pragma unroll
                for (int j = 0; j < 4; j++) o[i][j] += pp[i] * vv[j];
        }
    }

    // Normalize and write y[b, q0+r, h*64 + dcol]
#pragma unroll
    for (int i = 0; i < 4; i++) {
        const int r = q0 + ty * 4 + i;
        const float inv = 1.f / l[i];
        float4 ov = make_float4(o[i][0] * inv, o[i][1] * inv,
                                o[i][2] * inv, o[i][3] * inv);
        *(float4*)&y[((size_t)(b * TT + r)) * TC + h * HD + tx * 4] = ov;
    }
}

// ---------------------------------------------------------------------------
extern "C" void kernel_launch(void* const* d_in, const int* in_sizes, int n_in,
                              void* d_out, int out_size) {
    const float* x  = (const float*)d_in[0];   // [2,2048,1024]
    const float* Wa = (const float*)d_in[1];   // [1024,3072]
    const float* Wp = (const float*)d_in[2];   // [1024,1024]
    float* out = (float*)d_out;                // [2,2048,1024]

    float *qkv, *y;
    cudaGetSymbolAddress((void**)&qkv, g_qkv);
    cudaGetSymbolAddress((void**)&y, g_y);

    const int smem_attn = 4 * 64 * 65 * (int)sizeof(float);  // 66560 B
    cudaFuncSetAttribute(attn64, cudaFuncAttributeMaxDynamicSharedMemorySize,
                         smem_attn);

    // qkv = x @ W_attn   [4096 x 3072]
    dim3 g1(3 * TC / 64, BT / 64);
    sgemm64<<<g1, 256>>>(x, Wa, qkv, BT, 3 * TC, TC);

    // causal attention -> y [4096 x 1024]
    dim3 ga(TT / 64, TH, TB);
    attn64<<<ga, 256, smem_attn>>>(qkv, y);

    // out = y @ W_proj   [4096 x 1024]
    dim3 g2(TC / 64, BT / 64);
    sgemm64<<<g2, 256>>>(y, Wp, out, BT, TC, TC);
}

// round 3
// speedup vs baseline: 1.4412x; 1.4412x over previous
#include <cuda_runtime.h>
#include <cuda_bf16.h>
#include <cstdint>
#include <math.h>

#define TB 2
#define TT 2048
#define TC 1024
#define TH 16
#define HD 64
#define BT (TB*TT)     // 4096 rows
#define KP 3072        // packed K' = 3*1024

// ---------------- scratch (allocation-free) ----------------
__device__ float g_qkv[(size_t)BT * 3 * TC];            // 48 MB
__device__ float g_y[(size_t)BT * TC];                  // 16 MB
__device__ __nv_bfloat16 g_xp[(size_t)BT * KP];         // x packed [hi|hi|lo]   24 MB
__device__ __nv_bfloat16 g_yp[(size_t)BT * KP];         // y packed              24 MB
__device__ __nv_bfloat16 g_wap[(size_t)3 * TC * KP];    // W_attn^T packed [hi|lo|hi] 18 MB
__device__ __nv_bfloat16 g_wpp[(size_t)TC * KP];        // W_proj^T packed        6 MB

__device__ __forceinline__ uint32_t smem_u32(const void* p) {
    uint32_t a;
    asm("{ .reg .u64 t; cvta.to.shared.u64 t, %1; cvt.u32.u64 %0, t; }" : "=r"(a) : "l"(p));
    return a;
}

// ---------------- convert kernels ----------------
// rows x 1024 fp32 -> rows x 3072 bf16 packed as [hi | hi | lo]
__global__ void conv_a_packed(const float4* __restrict__ s,
                              __nv_bfloat16* __restrict__ d, int rows) {
    int i = blockIdx.x * 256 + threadIdx.x;        // over rows*256 float4 chunks
    if (i >= rows * 256) return;
    int row = i >> 8, c = (i & 255) * 4;
    float4 f = s[i];
    __nv_bfloat162 h0 = __floats2bfloat162_rn(f.x, f.y);
    __nv_bfloat162 h1 = __floats2bfloat162_rn(f.z, f.w);
    float2 a = __bfloat1622float2(h0), b = __bfloat1622float2(h1);
    __nv_bfloat162 l0 = __floats2bfloat162_rn(f.x - a.x, f.y - a.y);
    __nv_bfloat162 l1 = __floats2bfloat162_rn(f.z - b.x, f.w - b.y);
    __nv_bfloat16* p = d + (size_t)row * KP + c;
    *(__nv_bfloat162*)(p)              = h0; *(__nv_bfloat162*)(p + 2)        = h1;
    *(__nv_bfloat162*)(p + 1024)       = h0; *(__nv_bfloat162*)(p + 1026)     = h1;
    *(__nv_bfloat162*)(p + 2048)       = l0; *(__nv_bfloat162*)(p + 2050)     = l1;
}

// W[K=1024][N] fp32 -> Wp[n][3072] bf16 packed as [hi | lo | hi]
__global__ void conv_b_packed(const float* __restrict__ W,
                              __nv_bfloat16* __restrict__ d, int N) {
    __shared__ float t[32][33];
    const int k0 = blockIdx.y * 32, n0 = blockIdx.x * 32;
    const int tx = threadIdx.x, ty = threadIdx.y;
#pragma unroll
    for (int i = 0; i < 32; i += 8)
        t[ty + i][tx] = W[(size_t)(k0 + ty + i) * N + n0 + tx];
    __syncthreads();
#pragma unroll
    for (int i = 0; i < 32; i += 8) {
        float f = t[tx][ty + i];
        __nv_bfloat16 hb = __float2bfloat16(f);
        __nv_bfloat16 lb = __float2bfloat16(f - __bfloat162float(hb));
        __nv_bfloat16* p = d + (size_t)(n0 + ty + i) * KP + k0 + tx;
        p[0]    = hb;
        p[1024] = lb;
        p[2048] = hb;
    }
}

// ---------------- warp-MMA bf16 GEMM (HMMA.16816) ----------------
// C[M,N] = Apacked[M,KP] @ Bpacked[N,KP]^T, fp32 out.
// CTA tile 128x256, 256 threads = 8 warps (2 m-rows x 4 n-cols of 64x64).
#define BM 128
#define BN 256
#define BK 32
#define LDA 40                     // bf16 elems/row in smem (32 + 8 pad -> 80B rows)
#define A_BUF (BM * LDA)           // 5120 bf16
#define B_BUF (BN * LDA)           // 10240 bf16
#define GEMM_SMEM ((2 * (A_BUF + B_BUF)) * 2)   // 61440 bytes

__device__ __forceinline__ void ldmx4(uint32_t* r, uint32_t addr) {
    asm volatile("ldmatrix.sync.aligned.m8n8.x4.shared.b16 {%0,%1,%2,%3}, [%4];"
        : "=r"(r[0]), "=r"(r[1]), "=r"(r[2]), "=r"(r[3]) : "r"(addr));
}
__device__ __forceinline__ void mma16816(float* c, const uint32_t* a, const uint32_t* b) {
    asm volatile("mma.sync.aligned.m16n8k16.row.col.f32.bf16.bf16.f32 "
        "{%0,%1,%2,%3}, {%4,%5,%6,%7}, {%8,%9}, {%0,%1,%2,%3};"
        : "+f"(c[0]), "+f"(c[1]), "+f"(c[2]), "+f"(c[3])
        : "r"(a[0]), "r"(a[1]), "r"(a[2]), "r"(a[3]), "r"(b[0]), "r"(b[1]));
}

__global__ __launch_bounds__(256, 1)
void gemm_hmma(const __nv_bfloat16* __restrict__ A,
               const __nv_bfloat16* __restrict__ B,
               float* __restrict__ C, int N) {
    extern __shared__ __nv_bfloat16 smb[];
    const int tid = threadIdx.x, wid = tid >> 5, lane = tid & 31;
    const int m0 = blockIdx.y * BM, n0 = blockIdx.x * BN;
    const int wm0 = (wid >> 2) * 64, wn0 = (wid & 3) * 64;

    float acc[4][8][4];
#pragma unroll
    for (int f = 0; f < 4; f++)
#pragma unroll
        for (int j = 0; j < 8; j++)
#pragma unroll
            for (int e = 0; e < 4; e++) acc[f][j][e] = 0.f;

    const uint4* Ag = (const uint4*)A;
    const uint4* Bg = (const uint4*)B;
    const int KU = KP / 8;                 // uint4 per gmem row
    const int NST = KP / BK;               // 96 stages

    // per-thread load slots: A 2x, B 4x (each uint4 = 8 bf16)
    const int arow[2] = { (tid + 0) >> 2, (tid + 256) >> 2 };
    const int ach = tid & 3;
    int brow[4];
#pragma unroll
    for (int j = 0; j < 4; j++) brow[j] = (tid + j * 256) >> 2;

    uint4 ra[2], rb[4];
    auto ldg = [&](int s) {
        const int kc = s * (BK / 8);
#pragma unroll
        for (int j = 0; j < 2; j++) ra[j] = Ag[(size_t)(m0 + arow[j]) * KU + kc + ach];
#pragma unroll
        for (int j = 0; j < 4; j++) rb[j] = Bg[(size_t)(n0 + brow[j]) * KU + kc + ach];
    };
    auto sts = [&](int b) {
        __nv_bfloat16* As = smb + b * A_BUF;
        __nv_bfloat16* Bs = smb + 2 * A_BUF + b * B_BUF;
#pragma unroll
        for (int j = 0; j < 2; j++) *(uint4*)&As[arow[j] * LDA + ach * 8] = ra[j];
#pragma unroll
        for (int j = 0; j < 4; j++) *(uint4*)&Bs[brow[j] * LDA + ach * 8] = rb[j];
    };

    // ldmatrix lane addressing (byte offsets within tile, row stride 80B)
    const int a_r = lane & 15, a_c = (lane >> 4) * 8;           // A frags
    const int b_n = ((lane >> 4) & 1) * 8 + (lane & 7);         // B frag pairs
    const int b_k = ((lane >> 3) & 1) * 8;

    ldg(0); sts(0); __syncthreads();
    ldg(1);

#pragma unroll 1
    for (int s = 0; s < NST; ++s) {
        const int b = s & 1;
        const uint32_t As0 = smem_u32(smb + b * A_BUF);
        const uint32_t Bs0 = smem_u32(smb + 2 * A_BUF + b * B_BUF);

#pragma unroll
        for (int ks = 0; ks < 2; ++ks) {
            const int k0 = ks * 16;
            uint32_t afr[4][4], bfr[8][2];
#pragma unroll
            for (int f = 0; f < 4; f++) {
                uint32_t addr = As0 + (uint32_t)((wm0 + f * 16 + a_r) * 80 + (k0 + a_c) * 2);
                ldmx4(afr[f], addr);
            }
#pragma unroll
            for (int p = 0; p < 4; p++) {
                uint32_t r[4];
                uint32_t addr = Bs0 + (uint32_t)((wn0 + p * 16 + b_n) * 80 + (k0 + b_k) * 2);
                ldmx4(r, addr);
                bfr[2 * p][0] = r[0]; bfr[2 * p][1] = r[1];
                bfr[2 * p + 1][0] = r[2]; bfr[2 * p + 1][1] = r[3];
            }
#pragma unroll
            for (int f = 0; f < 4; f++)
#pragma unroll
                for (int j = 0; j < 8; j++)
                    mma16816(acc[f][j], afr[f], bfr[j]);
        }

        __syncthreads();
        if (s + 1 < NST) {
            sts((s + 1) & 1);
            __syncthreads();
            if (s + 2 < NST) ldg(s + 2);
        }
    }

    // epilogue: direct gmem stores (float2 per fragment half-row)
    const int er = lane >> 2, ec = (lane & 3) * 2;
#pragma unroll
    for (int f = 0; f < 4; f++) {
        const int row = m0 + wm0 + f * 16 + er;
#pragma unroll
        for (int j = 0; j < 8; j++) {
            const int col = n0 + wn0 + j * 8 + ec;
            *(float2*)&C[(size_t)row * N + col]       = make_float2(acc[f][j][0], acc[f][j][1]);
            *(float2*)&C[(size_t)(row + 8) * N + col] = make_float2(acc[f][j][2], acc[f][j][3]);
        }
    }
}

// ---------------- flash attention (fp32, unchanged) ----------------
__global__ __launch_bounds__(256) void attn64(const float* __restrict__ qkv,
                                              float* __restrict__ y) {
    extern __shared__ float smf[];
    float* Qs = smf;
    float* Ks = Qs + 64 * 65;
    float* Vs = Ks + 64 * 65;
    float* Ps = Vs + 64 * 65;

    const int qb = blockIdx.x, h = blockIdx.y, b = blockIdx.z;
    const int q0 = qb * 64;
    const int tid = threadIdx.x, tx = tid & 15, ty = tid >> 4;
    const size_t rowstride = 3 * TC;
    const float* base = qkv + (size_t)b * TT * rowstride + h * HD;

    for (int i = tid; i < 64 * 64; i += 256) {
        const int r = i >> 6, d = i & 63;
        Qs[r * 65 + d] = base[(size_t)(q0 + r) * rowstride + d];
    }

    float m[4], l[4], o[4][4];
#pragma unroll
    for (int i = 0; i < 4; i++) {
        m[i] = -1e30f; l[i] = 0.f;
#pragma unroll
        for (int j = 0; j < 4; j++) o[i][j] = 0.f;
    }

    for (int kt = 0; kt <= qb; ++kt) {
        const int k0 = kt * 64;
        __syncthreads();
        for (int i = tid; i < 64 * 64; i += 256) {
            const int r = i >> 6, d = i & 63;
            const float* p = base + (size_t)(k0 + r) * rowstride + d;
            Ks[r * 65 + d] = p[TC];
            Vs[r * 65 + d] = p[2 * TC];
        }
        __syncthreads();

        float s[4][4];
#pragma unroll
        for (int i = 0; i < 4; i++)
#pragma unroll
            for (int j = 0; j < 4; j++) s[i][j] = 0.f;
#pragma unroll 4
        for (int d = 0; d < 64; ++d) {
            float a[4], bb[4];
#pragma unroll
            for (int i = 0; i < 4; i++) a[i] = Qs[(ty * 4 + i) * 65 + d];
#pragma unroll
            for (int j = 0; j < 4; j++) bb[j] = Ks[(tx * 4 + j) * 65 + d];
#pragma unroll
            for (int i = 0; i < 4; i++)
#pragma unroll
                for (int j = 0; j < 4; j++) s[i][j] += a[i] * bb[j];
        }

        const bool diag = (kt == qb);
#pragma unroll
        for (int i = 0; i < 4; i++) {
            const int r = ty * 4 + i;
            float sv[4];
#pragma unroll
            for (int j = 0; j < 4; j++) {
                float v = s[i][j] * 0.125f;
                if (diag && (tx * 4 + j) > r) v = -1e30f;
                sv[j] = v;
            }
            float mloc = fmaxf(fmaxf(sv[0], sv[1]), fmaxf(sv[2], sv[3]));
#pragma unroll
            for (int off = 8; off >= 1; off >>= 1)
                mloc = fmaxf(mloc, __shfl_xor_sync(0xffffffffu, mloc, off));
            const float mnew = fmaxf(m[i], mloc);
            float p[4], rs = 0.f;
#pragma unroll
            for (int j = 0; j < 4; j++) { p[j] = __expf(sv[j] - mnew); rs += p[j]; }
#pragma unroll
            for (int off = 8; off >= 1; off >>= 1)
                rs += __shfl_xor_sync(0xffffffffu, rs, off);
            const float f = __expf(m[i] - mnew);
            l[i] = l[i] * f + rs;
            m[i] = mnew;
#pragma unroll
            for (int j = 0; j < 4; j++) o[i][j] *= f;
#pragma unroll
            for (int j = 0; j < 4; j++) Ps[r * 65 + tx * 4 + j] = p[j];
        }
        __syncthreads();

#pragma unroll 4
        for (int kc = 0; kc < 64; ++kc) {
            float pp[4], vv[4];
#pragma unroll
            for (int i = 0; i < 4; i++) pp[i] = Ps[(ty * 4 + i) * 65 + kc];
#pragma unroll
            for (int j = 0; j < 4; j++) vv[j] = Vs[kc * 65 + tx * 4 + j];
#pragma unroll
            for (int i = 0; i < 4; i++)
#pragma unroll
                for (int j = 0; j < 4; j++) o[i][j] += pp[i] * vv[j];
        }
    }

#pragma unroll
    for (int i = 0; i < 4; i++) {
        const int r = q0 + ty * 4 + i;
        const float inv = 1.f / l[i];
        float4 ov = make_float4(o[i][0] * inv, o[i][1] * inv, o[i][2] * inv, o[i][3] * inv);
        *(float4*)&y[((size_t)(b * TT + r)) * TC + h * HD + tx * 4] = ov;
    }
}

// ---------------------------------------------------------------------------
extern "C" void kernel_launch(void* const* d_in, const int* in_sizes, int n_in,
                              void* d_out, int out_size) {
    const float* x  = (const float*)d_in[0];
    const float* Wa = (const float*)d_in[1];
    const float* Wp = (const float*)d_in[2];
    float* out = (float*)d_out;

    float *qkv, *y;
    __nv_bfloat16 *xp, *yp, *wap, *wpp;
    cudaGetSymbolAddress((void**)&qkv, g_qkv);
    cudaGetSymbolAddress((void**)&y, g_y);
    cudaGetSymbolAddress((void**)&xp, g_xp);
    cudaGetSymbolAddress((void**)&yp, g_yp);
    cudaGetSymbolAddress((void**)&wap, g_wap);
    cudaGetSymbolAddress((void**)&wpp, g_wpp);

    cudaFuncSetAttribute(gemm_hmma, cudaFuncAttributeMaxDynamicSharedMemorySize, GEMM_SMEM);
    const int smem_attn = 4 * 64 * 65 * (int)sizeof(float);
    cudaFuncSetAttribute(attn64, cudaFuncAttributeMaxDynamicSharedMemorySize, smem_attn);

    // pack x
    conv_a_packed<<<(BT * 256 + 255) / 256, 256>>>((const float4*)x, xp, BT);
    // pack weights (transpose + split)
    {
        dim3 gw(3 * TC / 32, TC / 32);
        conv_b_packed<<<gw, dim3(32, 8)>>>(Wa, wap, 3 * TC);
        dim3 gp(TC / 32, TC / 32);
        conv_b_packed<<<gp, dim3(32, 8)>>>(Wp, wpp, TC);
    }
    // qkv = x @ W_attn
    {
        dim3 g(3 * TC / BN, BT / BM);
        gemm_hmma<<<g, 256, GEMM_SMEM>>>(xp, wap, qkv, 3 * TC);
    }
    // attention
    {
        dim3 ga(TT / 64, TH, TB);
        attn64<<<ga, 256, smem_attn>>>(qkv, y);
    }
    // pack y
    conv_a_packed<<<(BT * 256 + 255) / 256, 256>>>((const float4*)y, yp, BT);
    // out = y @ W_proj
    {
        dim3 g(TC / BN, BT / BM);
        gemm_hmma<<<g, 256, GEMM_SMEM>>>(yp, wpp, out, TC);
    }
}

// round 5
// speedup vs baseline: 2.4361x; 1.6904x over previous
#include <cuda_runtime.h>
#include <cuda_bf16.h>
#include <cstdint>
#include <math.h>

#define TB 2
#define TT 2048
#define TC 1024
#define TH 16
#define HD 64
#define BT (TB*TT)     // 4096 rows
#define KP 3072        // packed K' = 3*1024

// ---------------- scratch (allocation-free) ----------------
__device__ float g_qkv[(size_t)BT * 3 * TC];            // 48 MB
__device__ __nv_bfloat16 g_xp[(size_t)BT * KP];         // x packed [hi|hi|lo]
__device__ __nv_bfloat16 g_yp[(size_t)BT * KP];         // y packed [hi|hi|lo]
__device__ __nv_bfloat16 g_wap[(size_t)3 * TC * KP];    // W_attn^T packed [hi|lo|hi]
__device__ __nv_bfloat16 g_wpp[(size_t)TC * KP];        // W_proj^T packed [hi|lo|hi]

__device__ __forceinline__ uint32_t smem_u32(const void* p) {
    uint32_t a;
    asm("{ .reg .u64 t; cvta.to.shared.u64 t, %1; cvt.u32.u64 %0, t; }" : "=r"(a) : "l"(p));
    return a;
}
__device__ __forceinline__ void ldmx4(uint32_t* r, uint32_t addr) {
    asm volatile("ldmatrix.sync.aligned.m8n8.x4.shared.b16 {%0,%1,%2,%3}, [%4];"
        : "=r"(r[0]), "=r"(r[1]), "=r"(r[2]), "=r"(r[3]) : "r"(addr));
}
__device__ __forceinline__ void mma16816(float* c, const uint32_t* a, const uint32_t* b) {
    asm volatile("mma.sync.aligned.m16n8k16.row.col.f32.bf16.bf16.f32 "
        "{%0,%1,%2,%3}, {%4,%5,%6,%7}, {%8,%9}, {%0,%1,%2,%3};"
        : "+f"(c[0]), "+f"(c[1]), "+f"(c[2]), "+f"(c[3])
        : "r"(a[0]), "r"(a[1]), "r"(a[2]), "r"(a[3]), "r"(b[0]), "r"(b[1]));
}
// fp32 pair -> bf16 hi pair + bf16 lo pair (packed b32)
__device__ __forceinline__ void cvt_hl(float f0, float f1, uint32_t& h, uint32_t& l) {
    __nv_bfloat162 hb = __floats2bfloat162_rn(f0, f1);
    float2 hf = __bfloat1622float2(hb);
    __nv_bfloat162 lb = __floats2bfloat162_rn(f0 - hf.x, f1 - hf.y);
    h = *(uint32_t*)&hb;
    l = *(uint32_t*)&lb;
}

// ---------------- convert kernels ----------------
__global__ void conv_a_packed(const float4* __restrict__ s,
                              __nv_bfloat16* __restrict__ d, int rows) {
    int i = blockIdx.x * 256 + threadIdx.x;
    if (i >= rows * 256) return;
    int row = i >> 8, c = (i & 255) * 4;
    float4 f = s[i];
    __nv_bfloat162 h0 = __floats2bfloat162_rn(f.x, f.y);
    __nv_bfloat162 h1 = __floats2bfloat162_rn(f.z, f.w);
    float2 a = __bfloat1622float2(h0), b = __bfloat1622float2(h1);
    __nv_bfloat162 l0 = __floats2bfloat162_rn(f.x - a.x, f.y - a.y);
    __nv_bfloat162 l1 = __floats2bfloat162_rn(f.z - b.x, f.w - b.y);
    __nv_bfloat16* p = d + (size_t)row * KP + c;
    *(__nv_bfloat162*)(p)          = h0; *(__nv_bfloat162*)(p + 2)    = h1;
    *(__nv_bfloat162*)(p + 1024)   = h0; *(__nv_bfloat162*)(p + 1026) = h1;
    *(__nv_bfloat162*)(p + 2048)   = l0; *(__nv_bfloat162*)(p + 2050) = l1;
}

__global__ void conv_b_packed(const float* __restrict__ W,
                              __nv_bfloat16* __restrict__ d, int N) {
    __shared__ float t[32][33];
    const int k0 = blockIdx.y * 32, n0 = blockIdx.x * 32;
    const int tx = threadIdx.x, ty = threadIdx.y;
#pragma unroll
    for (int i = 0; i < 32; i += 8)
        t[ty + i][tx] = W[(size_t)(k0 + ty + i) * N + n0 + tx];
    __syncthreads();
#pragma unroll
    for (int i = 0; i < 32; i += 8) {
        float f = t[tx][ty + i];
        __nv_bfloat16 hb = __float2bfloat16(f);
        __nv_bfloat16 lb = __float2bfloat16(f - __bfloat162float(hb));
        __nv_bfloat16* p = d + (size_t)(n0 + ty + i) * KP + k0 + tx;
        p[0] = hb; p[1024] = lb; p[2048] = hb;
    }
}

// ---------------- warp-MMA bf16 GEMM (unchanged from R3, passing) ----------------
#define BM 128
#define BN 256
#define BK 32
#define LDA 40
#define A_BUF (BM * LDA)
#define B_BUF (BN * LDA)
#define GEMM_SMEM ((2 * (A_BUF + B_BUF)) * 2)

__global__ __launch_bounds__(256, 1)
void gemm_hmma(const __nv_bfloat16* __restrict__ A,
               const __nv_bfloat16* __restrict__ B,
               float* __restrict__ C, int N) {
    extern __shared__ __nv_bfloat16 smb[];
    const int tid = threadIdx.x, wid = tid >> 5, lane = tid & 31;
    const int m0 = blockIdx.y * BM, n0 = blockIdx.x * BN;
    const int wm0 = (wid >> 2) * 64, wn0 = (wid & 3) * 64;

    float acc[4][8][4];
#pragma unroll
    for (int f = 0; f < 4; f++)
#pragma unroll
        for (int j = 0; j < 8; j++)
#pragma unroll
            for (int e = 0; e < 4; e++) acc[f][j][e] = 0.f;

    const uint4* Ag = (const uint4*)A;
    const uint4* Bg = (const uint4*)B;
    const int KU = KP / 8;
    const int NST = KP / BK;

    const int arow[2] = { (tid + 0) >> 2, (tid + 256) >> 2 };
    const int ach = tid & 3;
    int brow[4];
#pragma unroll
    for (int j = 0; j < 4; j++) brow[j] = (tid + j * 256) >> 2;

    uint4 ra[2], rb[4];
    auto ldg = [&](int s) {
        const int kc = s * (BK / 8);
#pragma unroll
        for (int j = 0; j < 2; j++) ra[j] = Ag[(size_t)(m0 + arow[j]) * KU + kc + ach];
#pragma unroll
        for (int j = 0; j < 4; j++) rb[j] = Bg[(size_t)(n0 + brow[j]) * KU + kc + ach];
    };
    auto sts = [&](int b) {
        __nv_bfloat16* As = smb + b * A_BUF;
        __nv_bfloat16* Bs = smb + 2 * A_BUF + b * B_BUF;
#pragma unroll
        for (int j = 0; j < 2; j++) *(uint4*)&As[arow[j] * LDA + ach * 8] = ra[j];
#pragma unroll
        for (int j = 0; j < 4; j++) *(uint4*)&Bs[brow[j] * LDA + ach * 8] = rb[j];
    };

    const int a_r = lane & 15, a_c = (lane >> 4) * 8;
    const int b_n = ((lane >> 4) & 1) * 8 + (lane & 7);
    const int b_k = ((lane >> 3) & 1) * 8;

    ldg(0); sts(0); __syncthreads();
    ldg(1);

#pragma unroll 1
    for (int s = 0; s < NST; ++s) {
        const int b = s & 1;
        const uint32_t As0 = smem_u32(smb + b * A_BUF);
        const uint32_t Bs0 = smem_u32(smb + 2 * A_BUF + b * B_BUF);

#pragma unroll
        for (int ks = 0; ks < 2; ++ks) {
            const int k0 = ks * 16;
            uint32_t afr[4][4], bfr[8][2];
#pragma unroll
            for (int f = 0; f < 4; f++)
                ldmx4(afr[f], As0 + (uint32_t)((wm0 + f * 16 + a_r) * 80 + (k0 + a_c) * 2));
#pragma unroll
            for (int p = 0; p < 4; p++) {
                uint32_t r[4];
                ldmx4(r, Bs0 + (uint32_t)((wn0 + p * 16 + b_n) * 80 + (k0 + b_k) * 2));
                bfr[2 * p][0] = r[0]; bfr[2 * p][1] = r[1];
                bfr[2 * p + 1][0] = r[2]; bfr[2 * p + 1][1] = r[3];
            }
#pragma unroll
            for (int f = 0; f < 4; f++)
#pragma unroll
                for (int j = 0; j < 8; j++)
                    mma16816(acc[f][j], afr[f], bfr[j]);
        }

        __syncthreads();
        if (s + 1 < NST) {
            sts((s + 1) & 1);
            __syncthreads();
            if (s + 2 < NST) ldg(s + 2);
        }
    }

    const int er = lane >> 2, ec = (lane & 3) * 2;
#pragma unroll
    for (int f = 0; f < 4; f++) {
        const int row = m0 + wm0 + f * 16 + er;
#pragma unroll
        for (int j = 0; j < 8; j++) {
            const int col = n0 + wn0 + j * 8 + ec;
            *(float2*)&C[(size_t)row * N + col]       = make_float2(acc[f][j][0], acc[f][j][1]);
            *(float2*)&C[(size_t)(row + 8) * N + col] = make_float2(acc[f][j][2], acc[f][j][3]);
        }
    }
}

// ---------------- tensor-core flash attention (split-bf16) ----------------
#define AP 72                    // bf16 pitch (144B rows: 16B-aligned, conflict-free ldmatrix)
#define ATT_SMEM (((2*128*AP) + (4*64*AP)) * 2 + 64*65*4)   // 90368 B

__global__ __launch_bounds__(256, 1)
void attn_mma(const float* __restrict__ qkv, __nv_bfloat16* __restrict__ yp) {
    extern __shared__ char smc[];
    __nv_bfloat16* Qh = (__nv_bfloat16*)smc;
    __nv_bfloat16* Ql = Qh + 128 * AP;
    __nv_bfloat16* Kh = Ql + 128 * AP;
    __nv_bfloat16* Kl = Kh + 64 * AP;
    __nv_bfloat16* Vh = Kl + 64 * AP;      // V^T hi: [d][kc]
    __nv_bfloat16* Vl = Vh + 64 * AP;
    float* stg = (float*)(Vl + 64 * AP);   // [64][65] fp32 staging

    const int qb = blockIdx.x, h = blockIdx.y, b = blockIdx.z;
    const int q0 = qb * 128;
    const int tid = threadIdx.x, wid = tid >> 5, lane = tid & 31;
    const int wq = wid * 16;
    const size_t rs = 3 * TC;
    const float* base = qkv + (size_t)b * TT * rs + h * HD;

    const int a_r = lane & 15, a_c = (lane >> 4) * 8;
    const int b_n = ((lane >> 4) & 1) * 8 + (lane & 7);
    const int b_k = ((lane >> 3) & 1) * 8;

    // load Q tile 128x64 -> hi/lo
#pragma unroll
    for (int p = 0; p < 8; ++p) {
        int i = tid + p * 256;
        int r = i >> 4, c4 = (i & 15) * 4;
        float4 f = *(const float4*)&base[(size_t)(q0 + r) * rs + c4];
        uint32_t h0, l0, h1, l1;
        cvt_hl(f.x, f.y, h0, l0);
        cvt_hl(f.z, f.w, h1, l1);
        *(uint32_t*)&Qh[r * AP + c4]     = h0; *(uint32_t*)&Qh[r * AP + c4 + 2] = h1;
        *(uint32_t*)&Ql[r * AP + c4]     = l0; *(uint32_t*)&Ql[r * AP + c4 + 2] = l1;
    }

    float mrow[2] = { -1e30f, -1e30f }, lrow[2] = { 0.f, 0.f };
    float oacc[8][4];
#pragma unroll
    for (int nb = 0; nb < 8; ++nb)
#pragma unroll
        for (int e = 0; e < 4; ++e) oacc[nb][e] = 0.f;

    const int nkt = qb * 2 + 2;
    for (int kt = 0; kt < nkt; ++kt) {
        const int k0 = kt * 64;
        __syncthreads();
        // K tile 64x64 -> Kh/Kl
#pragma unroll
        for (int p = 0; p < 4; ++p) {
            int i = tid + p * 256;
            int r = i >> 4, c4 = (i & 15) * 4;
            float4 f = *(const float4*)&base[(size_t)(k0 + r) * rs + TC + c4];
            uint32_t h0, l0, h1, l1;
            cvt_hl(f.x, f.y, h0, l0);
            cvt_hl(f.z, f.w, h1, l1);
            *(uint32_t*)&Kh[r * AP + c4]     = h0; *(uint32_t*)&Kh[r * AP + c4 + 2] = h1;
            *(uint32_t*)&Kl[r * AP + c4]     = l0; *(uint32_t*)&Kl[r * AP + c4 + 2] = l1;
        }
        // V tile 64x64 -> stage fp32 (SCALAR stores: pitch 65*4B rows are not
        // 16B-aligned for odd rows — float4 here caused the R4 misaligned-address)
#pragma unroll
        for (int p = 0; p < 4; ++p) {
            int i = tid + p * 256;
            int r = i >> 4, c4 = (i & 15) * 4;
            float4 f = *(const float4*)&base[(size_t)(k0 + r) * rs + 2 * TC + c4];
            float* sp = &stg[r * 65 + c4];
            sp[0] = f.x; sp[1] = f.y; sp[2] = f.z; sp[3] = f.w;
        }
        __syncthreads();
        // transpose V -> Vh/Vl [d][kc]
#pragma unroll
        for (int p = 0; p < 16; ++p) {
            int i = tid + p * 256;
            int d = i >> 6, kc = i & 63;
            float f = stg[kc * 65 + d];
            __nv_bfloat16 hb = __float2bfloat16(f);
            Vh[d * AP + kc] = hb;
            Vl[d * AP + kc] = __float2bfloat16(f - __bfloat162float(hb));
        }
        __syncthreads();

        if (k0 > q0 + wq + 15) continue;   // warp tile fully masked

        // ---- S = Q K^T (split: QhKh + QhKl + QlKh) ----
        float sacc[8][4];
#pragma unroll
        for (int nb = 0; nb < 8; ++nb)
#pragma unroll
            for (int e = 0; e < 4; ++e) sacc[nb][e] = 0.f;

        const uint32_t Qh0 = smem_u32(Qh), Ql0 = smem_u32(Ql);
        const uint32_t Kh0 = smem_u32(Kh), Kl0 = smem_u32(Kl);
#pragma unroll
        for (int ks = 0; ks < 4; ++ks) {
            const int kk = ks * 16;
            uint32_t qh[4], ql[4];
            ldmx4(qh, Qh0 + (uint32_t)(((wq + a_r) * AP + kk + a_c) * 2));
            ldmx4(ql, Ql0 + (uint32_t)(((wq + a_r) * AP + kk + a_c) * 2));
#pragma unroll
            for (int p = 0; p < 4; ++p) {
                uint32_t kh[4], kl[4];
                const uint32_t boff = (uint32_t)(((p * 16 + b_n) * AP + kk + b_k) * 2);
                ldmx4(kh, Kh0 + boff);
                ldmx4(kl, Kl0 + boff);
                mma16816(sacc[2 * p],     qh, &kh[0]);
                mma16816(sacc[2 * p + 1], qh, &kh[2]);
                mma16816(sacc[2 * p],     qh, &kl[0]);
                mma16816(sacc[2 * p + 1], qh, &kl[2]);
                mma16816(sacc[2 * p],     ql, &kh[0]);
                mma16816(sacc[2 * p + 1], ql, &kh[2]);
            }
        }

        // ---- masked online softmax (in registers) ----
        const int grow0 = q0 + wq + (lane >> 2);
        const bool dmask = (k0 + 63) > (q0 + wq);
        float mloc0 = -1e30f, mloc1 = -1e30f;
#pragma unroll
        for (int nb = 0; nb < 8; ++nb) {
            const int col = k0 + nb * 8 + (lane & 3) * 2;
            float s0 = sacc[nb][0] * 0.125f, s1 = sacc[nb][1] * 0.125f;
            float s2 = sacc[nb][2] * 0.125f, s3 = sacc[nb][3] * 0.125f;
            if (dmask) {
                if (col     > grow0)     s0 = -1e30f;
                if (col + 1 > grow0)     s1 = -1e30f;
                if (col     > grow0 + 8) s2 = -1e30f;
                if (col + 1 > grow0 + 8) s3 = -1e30f;
            }
            sacc[nb][0] = s0; sacc[nb][1] = s1; sacc[nb][2] = s2; sacc[nb][3] = s3;
            mloc0 = fmaxf(mloc0, fmaxf(s0, s1));
            mloc1 = fmaxf(mloc1, fmaxf(s2, s3));
        }
        mloc0 = fmaxf(mloc0, __shfl_xor_sync(0xffffffffu, mloc0, 1));
        mloc0 = fmaxf(mloc0, __shfl_xor_sync(0xffffffffu, mloc0, 2));
        mloc1 = fmaxf(mloc1, __shfl_xor_sync(0xffffffffu, mloc1, 1));
        mloc1 = fmaxf(mloc1, __shfl_xor_sync(0xffffffffu, mloc1, 2));
        const float mn0 = fmaxf(mrow[0], mloc0);
        const float mn1 = fmaxf(mrow[1], mloc1);

        float sum0 = 0.f, sum1 = 0.f;
#pragma unroll
        for (int nb = 0; nb < 8; ++nb) {
            float e0 = __expf(sacc[nb][0] - mn0), e1 = __expf(sacc[nb][1] - mn0);
            float e2 = __expf(sacc[nb][2] - mn1), e3 = __expf(sacc[nb][3] - mn1);
            sacc[nb][0] = e0; sacc[nb][1] = e1; sacc[nb][2] = e2; sacc[nb][3] = e3;
            sum0 += e0 + e1; sum1 += e2 + e3;
        }
        sum0 += __shfl_xor_sync(0xffffffffu, sum0, 1);
        sum0 += __shfl_xor_sync(0xffffffffu, sum0, 2);
        sum1 += __shfl_xor_sync(0xffffffffu, sum1, 1);
        sum1 += __shfl_xor_sync(0xffffffffu, sum1, 2);

        const float sc0 = __expf(mrow[0] - mn0);
        const float sc1 = __expf(mrow[1] - mn1);
        lrow[0] = lrow[0] * sc0 + sum0;
        lrow[1] = lrow[1] * sc1 + sum1;
        mrow[0] = mn0; mrow[1] = mn1;
#pragma unroll
        for (int nb = 0; nb < 8; ++nb) {
            oacc[nb][0] *= sc0; oacc[nb][1] *= sc0;
            oacc[nb][2] *= sc1; oacc[nb][3] *= sc1;
        }

        // ---- P (regs) -> bf16 hi/lo A-frags ----
        uint32_t pfh[4][4], pfl[4][4];
#pragma unroll
        for (int c = 0; c < 4; ++c) {
            cvt_hl(sacc[2 * c][0],     sacc[2 * c][1],     pfh[c][0], pfl[c][0]);
            cvt_hl(sacc[2 * c][2],     sacc[2 * c][3],     pfh[c][1], pfl[c][1]);
            cvt_hl(sacc[2 * c + 1][0], sacc[2 * c + 1][1], pfh[c][2], pfl[c][2]);
            cvt_hl(sacc[2 * c + 1][2], sacc[2 * c + 1][3], pfh[c][3], pfl[c][3]);
        }

        // ---- O += P V (split: PhVh + PlVh + PhVl) ----
        const uint32_t Vh0 = smem_u32(Vh), Vl0 = smem_u32(Vl);
#pragma unroll
        for (int c = 0; c < 4; ++c) {
#pragma unroll
            for (int p = 0; p < 4; ++p) {
                uint32_t vh[4], vl[4];
                const uint32_t boff = (uint32_t)(((p * 16 + b_n) * AP + c * 16 + b_k) * 2);
                ldmx4(vh, Vh0 + boff);
                ldmx4(vl, Vl0 + boff);
                mma16816(oacc[2 * p],     pfh[c], &vh[0]);
                mma16816(oacc[2 * p + 1], pfh[c], &vh[2]);
                mma16816(oacc[2 * p],     pfl[c], &vh[0]);
                mma16816(oacc[2 * p + 1], pfl[c], &vh[2]);
                mma16816(oacc[2 * p],     pfh[c], &vl[0]);
                mma16816(oacc[2 * p + 1], pfh[c], &vl[2]);
            }
        }
    }

    // ---- finalize: normalize + write yp packed [hi|hi|lo] ----
    const float inv0 = 1.f / lrow[0], inv1 = 1.f / lrow[1];
    const int row0 = q0 + wq + (lane >> 2);
    const size_t rb0 = (size_t)(b * TT + row0) * KP + h * HD;
    const size_t rb1 = rb0 + (size_t)8 * KP;
#pragma unroll
    for (int nb = 0; nb < 8; ++nb) {
        const int d0 = nb * 8 + (lane & 3) * 2;
        uint32_t hh, ll;
        cvt_hl(oacc[nb][0] * inv0, oacc[nb][1] * inv0, hh, ll);
        *(uint32_t*)&yp[rb0 + d0]        = hh;
        *(uint32_t*)&yp[rb0 + 1024 + d0] = hh;
        *(uint32_t*)&yp[rb0 + 2048 + d0] = ll;
        cvt_hl(oacc[nb][2] * inv1, oacc[nb][3] * inv1, hh, ll);
        *(uint32_t*)&yp[rb1 + d0]        = hh;
        *(uint32_t*)&yp[rb1 + 1024 + d0] = hh;
        *(uint32_t*)&yp[rb1 + 2048 + d0] = ll;
    }
}

// ---------------------------------------------------------------------------
extern "C" void kernel_launch(void* const* d_in, const int* in_sizes, int n_in,
                              void* d_out, int out_size) {
    const float* x  = (const float*)d_in[0];
    const float* Wa = (const float*)d_in[1];
    const float* Wp = (const float*)d_in[2];
    float* out = (float*)d_out;

    float* qkv;
    __nv_bfloat16 *xp, *yp, *wap, *wpp;
    cudaGetSymbolAddress((void**)&qkv, g_qkv);
    cudaGetSymbolAddress((void**)&xp, g_xp);
    cudaGetSymbolAddress((void**)&yp, g_yp);
    cudaGetSymbolAddress((void**)&wap, g_wap);
    cudaGetSymbolAddress((void**)&wpp, g_wpp);

    cudaFuncSetAttribute(gemm_hmma, cudaFuncAttributeMaxDynamicSharedMemorySize, GEMM_SMEM);
    cudaFuncSetAttribute(attn_mma, cudaFuncAttributeMaxDynamicSharedMemorySize, ATT_SMEM);

    conv_a_packed<<<(BT * 256 + 255) / 256, 256>>>((const float4*)x, xp, BT);
    {
        dim3 gw(3 * TC / 32, TC / 32);
        conv_b_packed<<<gw, dim3(32, 8)>>>(Wa, wap, 3 * TC);
        dim3 gp(TC / 32, TC / 32);
        conv_b_packed<<<gp, dim3(32, 8)>>>(Wp, wpp, TC);
    }
    {
        dim3 g(3 * TC / BN, BT / BM);
        gemm_hmma<<<g, 256, GEMM_SMEM>>>(xp, wap, qkv, 3 * TC);
    }
    {
        dim3 ga(TT / 128, TH, TB);
        attn_mma<<<ga, 256, ATT_SMEM>>>(qkv, yp);
    }
    {
        dim3 g(TC / BN, BT / BM);
        gemm_hmma<<<g, 256, GEMM_SMEM>>>(yp, wpp, out, TC);
    }
}

// round 6
// speedup vs baseline: 2.6489x; 1.0873x over previous
#include <cuda_runtime.h>
#include <cuda_bf16.h>
#include <cstdint>
#include <math.h>

#define TB 2
#define TT 2048
#define TC 1024
#define TH 16
#define HD 64
#define BT (TB*TT)     // 4096 rows
#define KP 3072        // packed K' = 3*1024

// ---------------- scratch (allocation-free) ----------------
__device__ float g_qkv[(size_t)BT * 3 * TC];            // 48 MB
__device__ __nv_bfloat16 g_xp[(size_t)BT * KP];         // x packed [hi|hi|lo]
__device__ __nv_bfloat16 g_yp[(size_t)BT * KP];         // y packed [hi|hi|lo]
__device__ __nv_bfloat16 g_wap[(size_t)3 * TC * KP];    // W_attn^T packed [hi|lo|hi]
__device__ __nv_bfloat16 g_wpp[(size_t)TC * KP];        // W_proj^T packed [hi|lo|hi]

__device__ __forceinline__ uint32_t smem_u32(const void* p) {
    uint32_t a;
    asm("{ .reg .u64 t; cvta.to.shared.u64 t, %1; cvt.u32.u64 %0, t; }" : "=r"(a) : "l"(p));
    return a;
}
__device__ __forceinline__ void ldmx4(uint32_t* r, uint32_t addr) {
    asm volatile("ldmatrix.sync.aligned.m8n8.x4.shared.b16 {%0,%1,%2,%3}, [%4];"
        : "=r"(r[0]), "=r"(r[1]), "=r"(r[2]), "=r"(r[3]) : "r"(addr));
}
__device__ __forceinline__ void mma16816(float* c, const uint32_t* a, const uint32_t* b) {
    asm volatile("mma.sync.aligned.m16n8k16.row.col.f32.bf16.bf16.f32 "
        "{%0,%1,%2,%3}, {%4,%5,%6,%7}, {%8,%9}, {%0,%1,%2,%3};"
        : "+f"(c[0]), "+f"(c[1]), "+f"(c[2]), "+f"(c[3])
        : "r"(a[0]), "r"(a[1]), "r"(a[2]), "r"(a[3]), "r"(b[0]), "r"(b[1]));
}
__device__ __forceinline__ void cp_async16(uint32_t smem, const void* g) {
    asm volatile("cp.async.cg.shared.global [%0], [%1], 16;" :: "r"(smem), "l"(g));
}
#define CP_COMMIT() asm volatile("cp.async.commit_group;" ::: "memory")
#define CP_WAIT(n)  asm volatile("cp.async.wait_group %0;" :: "n"(n) : "memory")

// fp32 pair -> bf16 hi pair + bf16 lo pair (packed b32)
__device__ __forceinline__ void cvt_hl(float f0, float f1, uint32_t& h, uint32_t& l) {
    __nv_bfloat162 hb = __floats2bfloat162_rn(f0, f1);
    float2 hf = __bfloat1622float2(hb);
    __nv_bfloat162 lb = __floats2bfloat162_rn(f0 - hf.x, f1 - hf.y);
    h = *(uint32_t*)&hb;
    l = *(uint32_t*)&lb;
}

// ---------------- convert kernels ----------------
__global__ void conv_a_packed(const float4* __restrict__ s,
                              __nv_bfloat16* __restrict__ d, int rows) {
    int i = blockIdx.x * 256 + threadIdx.x;
    if (i >= rows * 256) return;
    int row = i >> 8, c = (i & 255) * 4;
    float4 f = s[i];
    __nv_bfloat162 h0 = __floats2bfloat162_rn(f.x, f.y);
    __nv_bfloat162 h1 = __floats2bfloat162_rn(f.z, f.w);
    float2 a = __bfloat1622float2(h0), b = __bfloat1622float2(h1);
    __nv_bfloat162 l0 = __floats2bfloat162_rn(f.x - a.x, f.y - a.y);
    __nv_bfloat162 l1 = __floats2bfloat162_rn(f.z - b.x, f.w - b.y);
    __nv_bfloat16* p = d + (size_t)row * KP + c;
    *(__nv_bfloat162*)(p)          = h0; *(__nv_bfloat162*)(p + 2)    = h1;
    *(__nv_bfloat162*)(p + 1024)   = h0; *(__nv_bfloat162*)(p + 1026) = h1;
    *(__nv_bfloat162*)(p + 2048)   = l0; *(__nv_bfloat162*)(p + 2050) = l1;
}

__global__ void conv_b_packed(const float* __restrict__ W,
                              __nv_bfloat16* __restrict__ d, int N) {
    __shared__ float t[32][33];
    const int k0 = blockIdx.y * 32, n0 = blockIdx.x * 32;
    const int tx = threadIdx.x, ty = threadIdx.y;
#pragma unroll
    for (int i = 0; i < 32; i += 8)
        t[ty + i][tx] = W[(size_t)(k0 + ty + i) * N + n0 + tx];
    __syncthreads();
#pragma unroll
    for (int i = 0; i < 32; i += 8) {
        float f = t[tx][ty + i];
        __nv_bfloat16 hb = __float2bfloat16(f);
        __nv_bfloat16 lb = __float2bfloat16(f - __bfloat162float(hb));
        __nv_bfloat16* p = d + (size_t)(n0 + ty + i) * KP + k0 + tx;
        p[0] = hb; p[1024] = lb; p[2048] = hb;
    }
}

// ---------------- warp-MMA bf16 GEMM, 4-stage cp.async pipeline ----------------
#define BM 128
#define BN 256
#define BK 32
#define LDA 40                          // bf16/row (80B rows, 16B-aligned)
#define A_BYTES (BM * LDA * 2)          // 10240
#define B_BYTES (BN * LDA * 2)          // 20480
#define STG_STRIDE (A_BYTES + B_BYTES)  // 30720
#define NSTG 4
#define GEMM_SMEM (NSTG * STG_STRIDE)   // 122880

__global__ __launch_bounds__(256, 1)
void gemm_hmma(const __nv_bfloat16* __restrict__ A,
               const __nv_bfloat16* __restrict__ B,
               float* __restrict__ C, int N) {
    extern __shared__ __nv_bfloat16 smb[];
    const uint32_t sbase = smem_u32(smb);
    const int tid = threadIdx.x, wid = tid >> 5, lane = tid & 31;
    const int m0 = blockIdx.y * BM, n0 = blockIdx.x * BN;
    const int wm0 = (wid >> 2) * 64, wn0 = (wid & 3) * 64;

    float acc[4][8][4];
#pragma unroll
    for (int f = 0; f < 4; f++)
#pragma unroll
        for (int j = 0; j < 8; j++)
#pragma unroll
            for (int e = 0; e < 4; e++) acc[f][j][e] = 0.f;

    const uint4* Ag = (const uint4*)A;
    const uint4* Bg = (const uint4*)B;
    const int KU = KP / 8;
    const int NST = KP / BK;              // 96

    const int arow[2] = { (tid + 0) >> 2, (tid + 256) >> 2 };
    const int ach = tid & 3;
    int brow[4];
#pragma unroll
    for (int j = 0; j < 4; j++) brow[j] = (tid + j * 256) >> 2;

    auto issue = [&](int s) {
        const int kc = s * (BK / 8);
        const uint32_t As = sbase + (uint32_t)(s & (NSTG - 1)) * STG_STRIDE;
        const uint32_t Bs = As + A_BYTES;
#pragma unroll
        for (int j = 0; j < 2; j++)
            cp_async16(As + (uint32_t)((arow[j] * LDA + ach * 8) * 2),
                       &Ag[(size_t)(m0 + arow[j]) * KU + kc + ach]);
#pragma unroll
        for (int j = 0; j < 4; j++)
            cp_async16(Bs + (uint32_t)((brow[j] * LDA + ach * 8) * 2),
                       &Bg[(size_t)(n0 + brow[j]) * KU + kc + ach]);
    };

    const int a_r = lane & 15, a_c = (lane >> 4) * 8;
    const int b_n = ((lane >> 4) & 1) * 8 + (lane & 7);
    const int b_k = ((lane >> 3) & 1) * 8;

#pragma unroll
    for (int s = 0; s < NSTG - 1; ++s) { issue(s); CP_COMMIT(); }

#pragma unroll 1
    for (int s = 0; s < NST; ++s) {
        CP_WAIT(NSTG - 2);
        __syncthreads();

        const uint32_t As0 = sbase + (uint32_t)(s & (NSTG - 1)) * STG_STRIDE;
        const uint32_t Bs0 = As0 + A_BYTES;

#pragma unroll
        for (int ks = 0; ks < 2; ++ks) {
            const int k0 = ks * 16;
            uint32_t afr[4][4], bfr[8][2];
#pragma unroll
            for (int f = 0; f < 4; f++)
                ldmx4(afr[f], As0 + (uint32_t)((wm0 + f * 16 + a_r) * 80 + (k0 + a_c) * 2));
#pragma unroll
            for (int p = 0; p < 4; p++) {
                uint32_t r[4];
                ldmx4(r, Bs0 + (uint32_t)((wn0 + p * 16 + b_n) * 80 + (k0 + b_k) * 2));
                bfr[2 * p][0] = r[0]; bfr[2 * p][1] = r[1];
                bfr[2 * p + 1][0] = r[2]; bfr[2 * p + 1][1] = r[3];
            }
#pragma unroll
            for (int f = 0; f < 4; f++)
#pragma unroll
                for (int j = 0; j < 8; j++)
                    mma16816(acc[f][j], afr[f], bfr[j]);
        }

        if (s + NSTG - 1 < NST) issue(s + NSTG - 1);
        CP_COMMIT();
    }

    const int er = lane >> 2, ec = (lane & 3) * 2;
#pragma unroll
    for (int f = 0; f < 4; f++) {
        const int row = m0 + wm0 + f * 16 + er;
#pragma unroll
        for (int j = 0; j < 8; j++) {
            const int col = n0 + wn0 + j * 8 + ec;
            *(float2*)&C[(size_t)row * N + col]       = make_float2(acc[f][j][0], acc[f][j][1]);
            *(float2*)&C[(size_t)(row + 8) * N + col] = make_float2(acc[f][j][2], acc[f][j][3]);
        }
    }
}

// ---------------- tensor-core flash attention (split-bf16, unchanged) ----------------
#define AP 72
#define ATT_SMEM (((2*128*AP) + (4*64*AP)) * 2 + 64*65*4)   // 90368 B

__global__ __launch_bounds__(256, 1)
void attn_mma(const float* __restrict__ qkv, __nv_bfloat16* __restrict__ yp) {
    extern __shared__ char smc[];
    __nv_bfloat16* Qh = (__nv_bfloat16*)smc;
    __nv_bfloat16* Ql = Qh + 128 * AP;
    __nv_bfloat16* Kh = Ql + 128 * AP;
    __nv_bfloat16* Kl = Kh + 64 * AP;
    __nv_bfloat16* Vh = Kl + 64 * AP;
    __nv_bfloat16* Vl = Vh + 64 * AP;
    float* stg = (float*)(Vl + 64 * AP);

    const int qb = blockIdx.x, h = blockIdx.y, b = blockIdx.z;
    const int q0 = qb * 128;
    const int tid = threadIdx.x, wid = tid >> 5, lane = tid & 31;
    const int wq = wid * 16;
    const size_t rs = 3 * TC;
    const float* base = qkv + (size_t)b * TT * rs + h * HD;

    const int a_r = lane & 15, a_c = (lane >> 4) * 8;
    const int b_n = ((lane >> 4) & 1) * 8 + (lane & 7);
    const int b_k = ((lane >> 3) & 1) * 8;

#pragma unroll
    for (int p = 0; p < 8; ++p) {
        int i = tid + p * 256;
        int r = i >> 4, c4 = (i & 15) * 4;
        float4 f = *(const float4*)&base[(size_t)(q0 + r) * rs + c4];
        uint32_t h0, l0, h1, l1;
        cvt_hl(f.x, f.y, h0, l0);
        cvt_hl(f.z, f.w, h1, l1);
        *(uint32_t*)&Qh[r * AP + c4]     = h0; *(uint32_t*)&Qh[r * AP + c4 + 2] = h1;
        *(uint32_t*)&Ql[r * AP + c4]     = l0; *(uint32_t*)&Ql[r * AP + c4 + 2] = l1;
    }

    float mrow[2] = { -1e30f, -1e30f }, lrow[2] = { 0.f, 0.f };
    float oacc[8][4];
#pragma unroll
    for (int nb = 0; nb < 8; ++nb)
#pragma unroll
        for (int e = 0; e < 4; ++e) oacc[nb][e] = 0.f;

    const int nkt = qb * 2 + 2;
    for (int kt = 0; kt < nkt; ++kt) {
        const int k0 = kt * 64;
        __syncthreads();
#pragma unroll
        for (int p = 0; p < 4; ++p) {
            int i = tid + p * 256;
            int r = i >> 4, c4 = (i & 15) * 4;
            float4 f = *(const float4*)&base[(size_t)(k0 + r) * rs + TC + c4];
            uint32_t h0, l0, h1, l1;
            cvt_hl(f.x, f.y, h0, l0);
            cvt_hl(f.z, f.w, h1, l1);
            *(uint32_t*)&Kh[r * AP + c4]     = h0; *(uint32_t*)&Kh[r * AP + c4 + 2] = h1;
            *(uint32_t*)&Kl[r * AP + c4]     = l0; *(uint32_t*)&Kl[r * AP + c4 + 2] = l1;
        }
#pragma unroll
        for (int p = 0; p < 4; ++p) {
            int i = tid + p * 256;
            int r = i >> 4, c4 = (i & 15) * 4;
            float4 f = *(const float4*)&base[(size_t)(k0 + r) * rs + 2 * TC + c4];
            float* sp = &stg[r * 65 + c4];
            sp[0] = f.x; sp[1] = f.y; sp[2] = f.z; sp[3] = f.w;
        }
        __syncthreads();
#pragma unroll
        for (int p = 0; p < 16; ++p) {
            int i = tid + p * 256;
            int d = i >> 6, kc = i & 63;
            float f = stg[kc * 65 + d];
            __nv_bfloat16 hb = __float2bfloat16(f);
            Vh[d * AP + kc] = hb;
            Vl[d * AP + kc] = __float2bfloat16(f - __bfloat162float(hb));
        }
        __syncthreads();

        if (k0 > q0 + wq + 15) continue;

        float sacc[8][4];
#pragma unroll
        for (int nb = 0; nb < 8; ++nb)
#pragma unroll
            for (int e = 0; e < 4; ++e) sacc[nb][e] = 0.f;

        const uint32_t Qh0 = smem_u32(Qh), Ql0 = smem_u32(Ql);
        const uint32_t Kh0 = smem_u32(Kh), Kl0 = smem_u32(Kl);
#pragma unroll
        for (int ks = 0; ks < 4; ++ks) {
            const int kk = ks * 16;
            uint32_t qh[4], ql[4];
            ldmx4(qh, Qh0 + (uint32_t)(((wq + a_r) * AP + kk + a_c) * 2));
            ldmx4(ql, Ql0 + (uint32_t)(((wq + a_r) * AP + kk + a_c) * 2));
#pragma unroll
            for (int p = 0; p < 4; ++p) {
                uint32_t kh[4], kl[4];
                const uint32_t boff = (uint32_t)(((p * 16 + b_n) * AP + kk + b_k) * 2);
                ldmx4(kh, Kh0 + boff);
                ldmx4(kl, Kl0 + boff);
                mma16816(sacc[2 * p],     qh, &kh[0]);
                mma16816(sacc[2 * p + 1], qh, &kh[2]);
                mma16816(sacc[2 * p],     qh, &kl[0]);
                mma16816(sacc[2 * p + 1], qh, &kl[2]);
                mma16816(sacc[2 * p],     ql, &kh[0]);
                mma16816(sacc[2 * p + 1], ql, &kh[2]);
            }
        }

        const int grow0 = q0 + wq + (lane >> 2);
        const bool dmask = (k0 + 63) > (q0 + wq);
        float mloc0 = -1e30f, mloc1 = -1e30f;
#pragma unroll
        for (int nb = 0; nb < 8; ++nb) {
            const int col = k0 + nb * 8 + (lane & 3) * 2;
            float s0 = sacc[nb][0] * 0.125f, s1 = sacc[nb][1] * 0.125f;
            float s2 = sacc[nb][2] * 0.125f, s3 = sacc[nb][3] * 0.125f;
            if (dmask) {
                if (col     > grow0)     s0 = -1e30f;
                if (col + 1 > grow0)     s1 = -1e30f;
                if (col     > grow0 + 8) s2 = -1e30f;
                if (col + 1 > grow0 + 8) s3 = -1e30f;
            }
            sacc[nb][0] = s0; sacc[nb][1] = s1; sacc[nb][2] = s2; sacc[nb][3] = s3;
            mloc0 = fmaxf(mloc0, fmaxf(s0, s1));
            mloc1 = fmaxf(mloc1, fmaxf(s2, s3));
        }
        mloc0 = fmaxf(mloc0, __shfl_xor_sync(0xffffffffu, mloc0, 1));
        mloc0 = fmaxf(mloc0, __shfl_xor_sync(0xffffffffu, mloc0, 2));
        mloc1 = fmaxf(mloc1, __shfl_xor_sync(0xffffffffu, mloc1, 1));
        mloc1 = fmaxf(mloc1, __shfl_xor_sync(0xffffffffu, mloc1, 2));
        const float mn0 = fmaxf(mrow[0], mloc0);
        const float mn1 = fmaxf(mrow[1], mloc1);

        float sum0 = 0.f, sum1 = 0.f;
#pragma unroll
        for (int nb = 0; nb < 8; ++nb) {
            float e0 = __expf(sacc[nb][0] - mn0), e1 = __expf(sacc[nb][1] - mn0);
            float e2 = __expf(sacc[nb][2] - mn1), e3 = __expf(sacc[nb][3] - mn1);
            sacc[nb][0] = e0; sacc[nb][1] = e1; sacc[nb][2] = e2; sacc[nb][3] = e3;
            sum0 += e0 + e1; sum1 += e2 + e3;
        }
        sum0 += __shfl_xor_sync(0xffffffffu, sum0, 1);
        sum0 += __shfl_xor_sync(0xffffffffu, sum0, 2);
        sum1 += __shfl_xor_sync(0xffffffffu, sum1, 1);
        sum1 += __shfl_xor_sync(0xffffffffu, sum1, 2);

        const float sc0 = __expf(mrow[0] - mn0);
        const float sc1 = __expf(mrow[1] - mn1);
        lrow[0] = lrow[0] * sc0 + sum0;
        lrow[1] = lrow[1] * sc1 + sum1;
        mrow[0] = mn0; mrow[1] = mn1;
#pragma unroll
        for (int nb = 0; nb < 8; ++nb) {
            oacc[nb][0] *= sc0; oacc[nb][1] *= sc0;
            oacc[nb][2] *= sc1; oacc[nb][3] *= sc1;
        }

        uint32_t pfh[4][4], pfl[4][4];
#pragma unroll
        for (int c = 0; c < 4; ++c) {
            cvt_hl(sacc[2 * c][0],     sacc[2 * c][1],     pfh[c][0], pfl[c][0]);
            cvt_hl(sacc[2 * c][2],     sacc[2 * c][3],     pfh[c][1], pfl[c][1]);
            cvt_hl(sacc[2 * c + 1][0], sacc[2 * c + 1][1], pfh[c][2], pfl[c][2]);
            cvt_hl(sacc[2 * c + 1][2], sacc[2 * c + 1][3], pfh[c][3], pfl[c][3]);
        }

        const uint32_t Vh0 = smem_u32(Vh), Vl0 = smem_u32(Vl);
#pragma unroll
        for (int c = 0; c < 4; ++c) {
#pragma unroll
            for (int p = 0; p < 4; ++p) {
                uint32_t vh[4], vl[4];
                const uint32_t boff = (uint32_t)(((p * 16 + b_n) * AP + c * 16 + b_k) * 2);
                ldmx4(vh, Vh0 + boff);
                ldmx4(vl, Vl0 + boff);
                mma16816(oacc[2 * p],     pfh[c], &vh[0]);
                mma16816(oacc[2 * p + 1], pfh[c], &vh[2]);
                mma16816(oacc[2 * p],     pfl[c], &vh[0]);
                mma16816(oacc[2 * p + 1], pfl[c], &vh[2]);
                mma16816(oacc[2 * p],     pfh[c], &vl[0]);
                mma16816(oacc[2 * p + 1], pfh[c], &vl[2]);
            }
        }
    }

    const float inv0 = 1.f / lrow[0], inv1 = 1.f / lrow[1];
    const int row0 = q0 + wq + (lane >> 2);
    const size_t rb0 = (size_t)(b * TT + row0) * KP + h * HD;
    const size_t rb1 = rb0 + (size_t)8 * KP;
#pragma unroll
    for (int nb = 0; nb < 8; ++nb) {
        const int d0 = nb * 8 + (lane & 3) * 2;
        uint32_t hh, ll;
        cvt_hl(oacc[nb][0] * inv0, oacc[nb][1] * inv0, hh, ll);
        *(uint32_t*)&yp[rb0 + d0]        = hh;
        *(uint32_t*)&yp[rb0 + 1024 + d0] = hh;
        *(uint32_t*)&yp[rb0 + 2048 + d0] = ll;
        cvt_hl(oacc[nb][2] * inv1, oacc[nb][3] * inv1, hh, ll);
        *(uint32_t*)&yp[rb1 + d0]        = hh;
        *(uint32_t*)&yp[rb1 + 1024 + d0] = hh;
        *(uint32_t*)&yp[rb1 + 2048 + d0] = ll;
    }
}

// ---------------------------------------------------------------------------
extern "C" void kernel_launch(void* const* d_in, const int* in_sizes, int n_in,
                              void* d_out, int out_size) {
    const float* x  = (const float*)d_in[0];
    const float* Wa = (const float*)d_in[1];
    const float* Wp = (const float*)d_in[2];
    float* out = (float*)d_out;

    float* qkv;
    __nv_bfloat16 *xp, *yp, *wap, *wpp;
    cudaGetSymbolAddress((void**)&qkv, g_qkv);
    cudaGetSymbolAddress((void**)&xp, g_xp);
    cudaGetSymbolAddress((void**)&yp, g_yp);
    cudaGetSymbolAddress((void**)&wap, g_wap);
    cudaGetSymbolAddress((void**)&wpp, g_wpp);

    cudaFuncSetAttribute(gemm_hmma, cudaFuncAttributeMaxDynamicSharedMemorySize, GEMM_SMEM);
    cudaFuncSetAttribute(attn_mma, cudaFuncAttributeMaxDynamicSharedMemorySize, ATT_SMEM);

    conv_a_packed<<<(BT * 256 + 255) / 256, 256>>>((const float4*)x, xp, BT);
    {
        dim3 gw(3 * TC / 32, TC / 32);
        conv_b_packed<<<gw, dim3(32, 8)>>>(Wa, wap, 3 * TC);
        dim3 gp(TC / 32, TC / 32);
        conv_b_packed<<<gp, dim3(32, 8)>>>(Wp, wpp, TC);
    }
    {
        dim3 g(3 * TC / BN, BT / BM);
        gemm_hmma<<<g, 256, GEMM_SMEM>>>(xp, wap, qkv, 3 * TC);
    }
    {
        dim3 ga(TT / 128, TH, TB);
        attn_mma<<<ga, 256, ATT_SMEM>>>(qkv, yp);
    }
    {
        dim3 g(TC / BN, BT / BM);
        gemm_hmma<<<g, 256, GEMM_SMEM>>>(yp, wpp, out, TC);
    }
}

// round 7
// speedup vs baseline: 2.7095x; 1.0229x over previous
#include <cuda_runtime.h>
#include <cuda_bf16.h>
#include <cstdint>
#include <math.h>

#define TB 2
#define TT 2048
#define TC 1024
#define TH 16
#define HD 64
#define BT (TB*TT)     // 4096 rows
#define KP 3072        // packed K' = 3*1024

// ---------------- scratch (allocation-free) ----------------
__device__ float g_qkv[(size_t)BT * 3 * TC];            // 48 MB
__device__ __nv_bfloat16 g_xp[(size_t)BT * KP];         // x packed [hi|hi|lo]
__device__ __nv_bfloat16 g_yp[(size_t)BT * KP];         // y packed [hi|hi|lo]
__device__ __nv_bfloat16 g_wap[(size_t)3 * TC * KP];    // W_attn^T packed [hi|lo|hi]
__device__ __nv_bfloat16 g_wpp[(size_t)TC * KP];        // W_proj^T packed [hi|lo|hi]

__device__ __forceinline__ uint32_t smem_u32(const void* p) {
    uint32_t a;
    asm("{ .reg .u64 t; cvta.to.shared.u64 t, %1; cvt.u32.u64 %0, t; }" : "=r"(a) : "l"(p));
    return a;
}
__device__ __forceinline__ void ldmx4(uint32_t* r, uint32_t addr) {
    asm volatile("ldmatrix.sync.aligned.m8n8.x4.shared.b16 {%0,%1,%2,%3}, [%4];"
        : "=r"(r[0]), "=r"(r[1]), "=r"(r[2]), "=r"(r[3]) : "r"(addr));
}
__device__ __forceinline__ void mma16816(float* c, const uint32_t* a, const uint32_t* b) {
    asm volatile("mma.sync.aligned.m16n8k16.row.col.f32.bf16.bf16.f32 "
        "{%0,%1,%2,%3}, {%4,%5,%6,%7}, {%8,%9}, {%0,%1,%2,%3};"
        : "+f"(c[0]), "+f"(c[1]), "+f"(c[2]), "+f"(c[3])
        : "r"(a[0]), "r"(a[1]), "r"(a[2]), "r"(a[3]), "r"(b[0]), "r"(b[1]));
}
__device__ __forceinline__ void cp_async16(uint32_t smem, const void* g) {
    asm volatile("cp.async.cg.shared.global [%0], [%1], 16;" :: "r"(smem), "l"(g));
}
#define CP_COMMIT() asm volatile("cp.async.commit_group;" ::: "memory")
#define CP_WAIT(n)  asm volatile("cp.async.wait_group %0;" :: "n"(n) : "memory")

// fp32 pair -> bf16 hi pair + bf16 lo pair (packed b32)
__device__ __forceinline__ void cvt_hl(float f0, float f1, uint32_t& h, uint32_t& l) {
    __nv_bfloat162 hb = __floats2bfloat162_rn(f0, f1);
    float2 hf = __bfloat1622float2(hb);
    __nv_bfloat162 lb = __floats2bfloat162_rn(f0 - hf.x, f1 - hf.y);
    h = *(uint32_t*)&hb;
    l = *(uint32_t*)&lb;
}

// ---------------- convert kernels ----------------
__global__ void conv_a_packed(const float4* __restrict__ s,
                              __nv_bfloat16* __restrict__ d, int rows) {
    int i = blockIdx.x * 256 + threadIdx.x;
    if (i >= rows * 256) return;
    int row = i >> 8, c = (i & 255) * 4;
    float4 f = s[i];
    __nv_bfloat162 h0 = __floats2bfloat162_rn(f.x, f.y);
    __nv_bfloat162 h1 = __floats2bfloat162_rn(f.z, f.w);
    float2 a = __bfloat1622float2(h0), b = __bfloat1622float2(h1);
    __nv_bfloat162 l0 = __floats2bfloat162_rn(f.x - a.x, f.y - a.y);
    __nv_bfloat162 l1 = __floats2bfloat162_rn(f.z - b.x, f.w - b.y);
    __nv_bfloat16* p = d + (size_t)row * KP + c;
    *(__nv_bfloat162*)(p)          = h0; *(__nv_bfloat162*)(p + 2)    = h1;
    *(__nv_bfloat162*)(p + 1024)   = h0; *(__nv_bfloat162*)(p + 1026) = h1;
    *(__nv_bfloat162*)(p + 2048)   = l0; *(__nv_bfloat162*)(p + 2050) = l1;
}

__global__ void conv_b_packed(const float* __restrict__ W,
                              __nv_bfloat16* __restrict__ d, int N) {
    __shared__ float t[32][33];
    const int k0 = blockIdx.y * 32, n0 = blockIdx.x * 32;
    const int tx = threadIdx.x, ty = threadIdx.y;
#pragma unroll
    for (int i = 0; i < 32; i += 8)
        t[ty + i][tx] = W[(size_t)(k0 + ty + i) * N + n0 + tx];
    __syncthreads();
#pragma unroll
    for (int i = 0; i < 32; i += 8) {
        float f = t[tx][ty + i];
        __nv_bfloat16 hb = __float2bfloat16(f);
        __nv_bfloat16 lb = __float2bfloat16(f - __bfloat162float(hb));
        __nv_bfloat16* p = d + (size_t)(n0 + ty + i) * KP + k0 + tx;
        p[0] = hb; p[1024] = lb; p[2048] = hb;
    }
}

// ---------------- warp-MMA bf16 GEMM: 512 threads, 16 warps, 4-stage cp.async ----
#define BM 128
#define BN 256
#define BK 32
#define LDA 40                          // bf16/row (80B rows, 16B-aligned)
#define A_BYTES (BM * LDA * 2)          // 10240
#define B_BYTES (BN * LDA * 2)          // 20480
#define STG_STRIDE (A_BYTES + B_BYTES)  // 30720
#define NSTG 4
#define GEMM_SMEM (NSTG * STG_STRIDE)   // 122880

__global__ __launch_bounds__(512, 1)
void gemm_hmma(const __nv_bfloat16* __restrict__ A,
               const __nv_bfloat16* __restrict__ B,
               float* __restrict__ C, int N) {
    extern __shared__ __nv_bfloat16 smb[];
    const uint32_t sbase = smem_u32(smb);
    const int tid = threadIdx.x, wid = tid >> 5, lane = tid & 31;
    const int m0 = blockIdx.y * BM, n0 = blockIdx.x * BN;
    const int wm0 = (wid >> 3) * 64;      // 2 m-rows of warps
    const int wn0 = (wid & 7) * 32;       // 8 n-cols of warps

    float acc[4][4][4];                    // [m16][n8][frag]
#pragma unroll
    for (int f = 0; f < 4; f++)
#pragma unroll
        for (int j = 0; j < 4; j++)
#pragma unroll
            for (int e = 0; e < 4; e++) acc[f][j][e] = 0.f;

    const uint4* Ag = (const uint4*)A;
    const uint4* Bg = (const uint4*)B;
    const int KU = KP / 8;
    const int NST = KP / BK;              // 96

    // A: 512 uint4 slots -> 1/thread; B: 1024 slots -> 2/thread
    const int arow = tid >> 2, ach = tid & 3;
    const int brow0 = tid >> 2, brow1 = (tid + 512) >> 2;

    auto issue = [&](int s) {
        const int kc = s * (BK / 8);
        const uint32_t As = sbase + (uint32_t)(s & (NSTG - 1)) * STG_STRIDE;
        const uint32_t Bs = As + A_BYTES;
        cp_async16(As + (uint32_t)((arow * LDA + ach * 8) * 2),
                   &Ag[(size_t)(m0 + arow) * KU + kc + ach]);
        cp_async16(Bs + (uint32_t)((brow0 * LDA + ach * 8) * 2),
                   &Bg[(size_t)(n0 + brow0) * KU + kc + ach]);
        cp_async16(Bs + (uint32_t)((brow1 * LDA + ach * 8) * 2),
                   &Bg[(size_t)(n0 + brow1) * KU + kc + ach]);
    };

    const int a_r = lane & 15, a_c = (lane >> 4) * 8;
    const int b_n = ((lane >> 4) & 1) * 8 + (lane & 7);
    const int b_k = ((lane >> 3) & 1) * 8;

#pragma unroll
    for (int s = 0; s < NSTG - 1; ++s) { issue(s); CP_COMMIT(); }

#pragma unroll 1
    for (int s = 0; s < NST; ++s) {
        CP_WAIT(NSTG - 2);
        __syncthreads();

        const uint32_t As0 = sbase + (uint32_t)(s & (NSTG - 1)) * STG_STRIDE;
        const uint32_t Bs0 = As0 + A_BYTES;

#pragma unroll
        for (int ks = 0; ks < 2; ++ks) {
            const int k0 = ks * 16;
            uint32_t afr[4][4], bfr[4][2];
#pragma unroll
            for (int f = 0; f < 4; f++)
                ldmx4(afr[f], As0 + (uint32_t)((wm0 + f * 16 + a_r) * 80 + (k0 + a_c) * 2));
#pragma unroll
            for (int p = 0; p < 2; p++) {
                uint32_t r[4];
                ldmx4(r, Bs0 + (uint32_t)((wn0 + p * 16 + b_n) * 80 + (k0 + b_k) * 2));
                bfr[2 * p][0] = r[0]; bfr[2 * p][1] = r[1];
                bfr[2 * p + 1][0] = r[2]; bfr[2 * p + 1][1] = r[3];
            }
#pragma unroll
            for (int f = 0; f < 4; f++)
#pragma unroll
                for (int j = 0; j < 4; j++)
                    mma16816(acc[f][j], afr[f], bfr[j]);
        }

        if (s + NSTG - 1 < NST) issue(s + NSTG - 1);
        CP_COMMIT();
    }

    const int er = lane >> 2, ec = (lane & 3) * 2;
#pragma unroll
    for (int f = 0; f < 4; f++) {
        const int row = m0 + wm0 + f * 16 + er;
#pragma unroll
        for (int j = 0; j < 4; j++) {
            const int col = n0 + wn0 + j * 8 + ec;
            *(float2*)&C[(size_t)row * N + col]       = make_float2(acc[f][j][0], acc[f][j][1]);
            *(float2*)&C[(size_t)(row + 8) * N + col] = make_float2(acc[f][j][2], acc[f][j][3]);
        }
    }
}

// ---------------- tensor-core flash attention (split-bf16, unchanged) ----------------
#define AP 72
#define ATT_SMEM (((2*128*AP) + (4*64*AP)) * 2 + 64*65*4)   // 90368 B

__global__ __launch_bounds__(256, 1)
void attn_mma(const float* __restrict__ qkv, __nv_bfloat16* __restrict__ yp) {
    extern __shared__ char smc[];
    __nv_bfloat16* Qh = (__nv_bfloat16*)smc;
    __nv_bfloat16* Ql = Qh + 128 * AP;
    __nv_bfloat16* Kh = Ql + 128 * AP;
    __nv_bfloat16* Kl = Kh + 64 * AP;
    __nv_bfloat16* Vh = Kl + 64 * AP;
    __nv_bfloat16* Vl = Vh + 64 * AP;
    float* stg = (float*)(Vl + 64 * AP);

    const int qb = blockIdx.x, h = blockIdx.y, b = blockIdx.z;
    const int q0 = qb * 128;
    const int tid = threadIdx.x, wid = tid >> 5, lane = tid & 31;
    const int wq = wid * 16;
    const size_t rs = 3 * TC;
    const float* base = qkv + (size_t)b * TT * rs + h * HD;

    const int a_r = lane & 15, a_c = (lane >> 4) * 8;
    const int b_n = ((lane >> 4) & 1) * 8 + (lane & 7);
    const int b_k = ((lane >> 3) & 1) * 8;

#pragma unroll
    for (int p = 0; p < 8; ++p) {
        int i = tid + p * 256;
        int r = i >> 4, c4 = (i & 15) * 4;
        float4 f = *(const float4*)&base[(size_t)(q0 + r) * rs + c4];
        uint32_t h0, l0, h1, l1;
        cvt_hl(f.x, f.y, h0, l0);
        cvt_hl(f.z, f.w, h1, l1);
        *(uint32_t*)&Qh[r * AP + c4]     = h0; *(uint32_t*)&Qh[r * AP + c4 + 2] = h1;
        *(uint32_t*)&Ql[r * AP + c4]     = l0; *(uint32_t*)&Ql[r * AP + c4 + 2] = l1;
    }

    float mrow[2] = { -1e30f, -1e30f }, lrow[2] = { 0.f, 0.f };
    float oacc[8][4];
#pragma unroll
    for (int nb = 0; nb < 8; ++nb)
#pragma unroll
        for (int e = 0; e < 4; ++e) oacc[nb][e] = 0.f;

    const int nkt = qb * 2 + 2;
    for (int kt = 0; kt < nkt; ++kt) {
        const int k0 = kt * 64;
        __syncthreads();
#pragma unroll
        for (int p = 0; p < 4; ++p) {
            int i = tid + p * 256;
            int r = i >> 4, c4 = (i & 15) * 4;
            float4 f = *(const float4*)&base[(size_t)(k0 + r) * rs + TC + c4];
            uint32_t h0, l0, h1, l1;
            cvt_hl(f.x, f.y, h0, l0);
            cvt_hl(f.z, f.w, h1, l1);
            *(uint32_t*)&Kh[r * AP + c4]     = h0; *(uint32_t*)&Kh[r * AP + c4 + 2] = h1;
            *(uint32_t*)&Kl[r * AP + c4]     = l0; *(uint32_t*)&Kl[r * AP + c4 + 2] = l1;
        }
#pragma unroll
        for (int p = 0; p < 4; ++p) {
            int i = tid + p * 256;
            int r = i >> 4, c4 = (i & 15) * 4;
            float4 f = *(const float4*)&base[(size_t)(k0 + r) * rs + 2 * TC + c4];
            float* sp = &stg[r * 65 + c4];
            sp[0] = f.x; sp[1] = f.y; sp[2] = f.z; sp[3] = f.w;
        }
        __syncthreads();
#pragma unroll
        for (int p = 0; p < 16; ++p) {
            int i = tid + p * 256;
            int d = i >> 6, kc = i & 63;
            float f = stg[kc * 65 + d];
            __nv_bfloat16 hb = __float2bfloat16(f);
            Vh[d * AP + kc] = hb;
            Vl[d * AP + kc] = __float2bfloat16(f - __bfloat162float(hb));
        }
        __syncthreads();

        if (k0 > q0 + wq + 15) continue;

        float sacc[8][4];
#pragma unroll
        for (int nb = 0; nb < 8; ++nb)
#pragma unroll
            for (int e = 0; e < 4; ++e) sacc[nb][e] = 0.f;

        const uint32_t Qh0 = smem_u32(Qh), Ql0 = smem_u32(Ql);
        const uint32_t Kh0 = smem_u32(Kh), Kl0 = smem_u32(Kl);
#pragma unroll
        for (int ks = 0; ks < 4; ++ks) {
            const int kk = ks * 16;
            uint32_t qh[4], ql[4];
            ldmx4(qh, Qh0 + (uint32_t)(((wq + a_r) * AP + kk + a_c) * 2));
            ldmx4(ql, Ql0 + (uint32_t)(((wq + a_r) * AP + kk + a_c) * 2));
#pragma unroll
            for (int p = 0; p < 4; ++p) {
                uint32_t kh[4], kl[4];
                const uint32_t boff = (uint32_t)(((p * 16 + b_n) * AP + kk + b_k) * 2);
                ldmx4(kh, Kh0 + boff);
                ldmx4(kl, Kl0 + boff);
                mma16816(sacc[2 * p],     qh, &kh[0]);
                mma16816(sacc[2 * p + 1], qh, &kh[2]);
                mma16816(sacc[2 * p],     qh, &kl[0]);
                mma16816(sacc[2 * p + 1], qh, &kl[2]);
                mma16816(sacc[2 * p],     ql, &kh[0]);
                mma16816(sacc[2 * p + 1], ql, &kh[2]);
            }
        }

        const int grow0 = q0 + wq + (lane >> 2);
        const bool dmask = (k0 + 63) > (q0 + wq);
        float mloc0 = -1e30f, mloc1 = -1e30f;
#pragma unroll
        for (int nb = 0; nb < 8; ++nb) {
            const int col = k0 + nb * 8 + (lane & 3) * 2;
            float s0 = sacc[nb][0] * 0.125f, s1 = sacc[nb][1] * 0.125f;
            float s2 = sacc[nb][2] * 0.125f, s3 = sacc[nb][3] * 0.125f;
            if (dmask) {
                if (col     > grow0)     s0 = -1e30f;
                if (col + 1 > grow0)     s1 = -1e30f;
                if (col     > grow0 + 8) s2 = -1e30f;
                if (col + 1 > grow0 + 8) s3 = -1e30f;
            }
            sacc[nb][0] = s0; sacc[nb][1] = s1; sacc[nb][2] = s2; sacc[nb][3] = s3;
            mloc0 = fmaxf(mloc0, fmaxf(s0, s1));
            mloc1 = fmaxf(mloc1, fmaxf(s2, s3));
        }
        mloc0 = fmaxf(mloc0, __shfl_xor_sync(0xffffffffu, mloc0, 1));
        mloc0 = fmaxf(mloc0, __shfl_xor_sync(0xffffffffu, mloc0, 2));
        mloc1 = fmaxf(mloc1, __shfl_xor_sync(0xffffffffu, mloc1, 1));
        mloc1 = fmaxf(mloc1, __shfl_xor_sync(0xffffffffu, mloc1, 2));
        const float mn0 = fmaxf(mrow[0], mloc0);
        const float mn1 = fmaxf(mrow[1], mloc1);

        float sum0 = 0.f, sum1 = 0.f;
#pragma unroll
        for (int nb = 0; nb < 8; ++nb) {
            float e0 = __expf(sacc[nb][0] - mn0), e1 = __expf(sacc[nb][1] - mn0);
            float e2 = __expf(sacc[nb][2] - mn1), e3 = __expf(sacc[nb][3] - mn1);
            sacc[nb][0] = e0; sacc[nb][1] = e1; sacc[nb][2] = e2; sacc[nb][3] = e3;
            sum0 += e0 + e1; sum1 += e2 + e3;
        }
        sum0 += __shfl_xor_sync(0xffffffffu, sum0, 1);
        sum0 += __shfl_xor_sync(0xffffffffu, sum0, 2);
        sum1 += __shfl_xor_sync(0xffffffffu, sum1, 1);
        sum1 += __shfl_xor_sync(0xffffffffu, sum1, 2);

        const float sc0 = __expf(mrow[0] - mn0);
        const float sc1 = __expf(mrow[1] - mn1);
        lrow[0] = lrow[0] * sc0 + sum0;
        lrow[1] = lrow[1] * sc1 + sum1;
        mrow[0] = mn0; mrow[1] = mn1;
#pragma unroll
        for (int nb = 0; nb < 8; ++nb) {
            oacc[nb][0] *= sc0; oacc[nb][1] *= sc0;
            oacc[nb][2] *= sc1; oacc[nb][3] *= sc1;
        }

        uint32_t pfh[4][4], pfl[4][4];
#pragma unroll
        for (int c = 0; c < 4; ++c) {
            cvt_hl(sacc[2 * c][0],     sacc[2 * c][1],     pfh[c][0], pfl[c][0]);
            cvt_hl(sacc[2 * c][2],     sacc[2 * c][3],     pfh[c][1], pfl[c][1]);
            cvt_hl(sacc[2 * c + 1][0], sacc[2 * c + 1][1], pfh[c][2], pfl[c][2]);
            cvt_hl(sacc[2 * c + 1][2], sacc[2 * c + 1][3], pfh[c][3], pfl[c][3]);
        }

        const uint32_t Vh0 = smem_u32(Vh), Vl0 = smem_u32(Vl);
#pragma unroll
        for (int c = 0; c < 4; ++c) {
#pragma unroll
            for (int p = 0; p < 4; ++p) {
                uint32_t vh[4], vl[4];
                const uint32_t boff = (uint32_t)(((p * 16 + b_n) * AP + c * 16 + b_k) * 2);
                ldmx4(vh, Vh0 + boff);
                ldmx4(vl, Vl0 + boff);
                mma16816(oacc[2 * p],     pfh[c], &vh[0]);
                mma16816(oacc[2 * p + 1], pfh[c], &vh[2]);
                mma16816(oacc[2 * p],     pfl[c], &vh[0]);
                mma16816(oacc[2 * p + 1], pfl[c], &vh[2]);
                mma16816(oacc[2 * p],     pfh[c], &vl[0]);
                mma16816(oacc[2 * p + 1], pfh[c], &vl[2]);
            }
        }
    }

    const float inv0 = 1.f / lrow[0], inv1 = 1.f / lrow[1];
    const int row0 = q0 + wq + (lane >> 2);
    const size_t rb0 = (size_t)(b * TT + row0) * KP + h * HD;
    const size_t rb1 = rb0 + (size_t)8 * KP;
#pragma unroll
    for (int nb = 0; nb < 8; ++nb) {
        const int d0 = nb * 8 + (lane & 3) * 2;
        uint32_t hh, ll;
        cvt_hl(oacc[nb][0] * inv0, oacc[nb][1] * inv0, hh, ll);
        *(uint32_t*)&yp[rb0 + d0]        = hh;
        *(uint32_t*)&yp[rb0 + 1024 + d0] = hh;
        *(uint32_t*)&yp[rb0 + 2048 + d0] = ll;
        cvt_hl(oacc[nb][2] * inv1, oacc[nb][3] * inv1, hh, ll);
        *(uint32_t*)&yp[rb1 + d0]        = hh;
        *(uint32_t*)&yp[rb1 + 1024 + d0] = hh;
        *(uint32_t*)&yp[rb1 + 2048 + d0] = ll;
    }
}

// ---------------------------------------------------------------------------
extern "C" void kernel_launch(void* const* d_in, const int* in_sizes, int n_in,
                              void* d_out, int out_size) {
    const float* x  = (const float*)d_in[0];
    const float* Wa = (const float*)d_in[1];
    const float* Wp = (const float*)d_in[2];
    float* out = (float*)d_out;

    float* qkv;
    __nv_bfloat16 *xp, *yp, *wap, *wpp;
    cudaGetSymbolAddress((void**)&qkv, g_qkv);
    cudaGetSymbolAddress((void**)&xp, g_xp);
    cudaGetSymbolAddress((void**)&yp, g_yp);
    cudaGetSymbolAddress((void**)&wap, g_wap);
    cudaGetSymbolAddress((void**)&wpp, g_wpp);

    cudaFuncSetAttribute(gemm_hmma, cudaFuncAttributeMaxDynamicSharedMemorySize, GEMM_SMEM);
    cudaFuncSetAttribute(attn_mma, cudaFuncAttributeMaxDynamicSharedMemorySize, ATT_SMEM);

    conv_a_packed<<<(BT * 256 + 255) / 256, 256>>>((const float4*)x, xp, BT);
    {
        dim3 gw(3 * TC / 32, TC / 32);
        conv_b_packed<<<gw, dim3(32, 8)>>>(Wa, wap, 3 * TC);
        dim3 gp(TC / 32, TC / 32);
        conv_b_packed<<<gp, dim3(32, 8)>>>(Wp, wpp, TC);
    }
    {
        dim3 g(3 * TC / BN, BT / BM);
        gemm_hmma<<<g, 512, GEMM_SMEM>>>(xp, wap, qkv, 3 * TC);
    }
    {
        dim3 ga(TT / 128, TH, TB);
        attn_mma<<<ga, 256, ATT_SMEM>>>(qkv, yp);
    }
    {
        dim3 g(TC / BN, BT / BM);
        gemm_hmma<<<g, 512, GEMM_SMEM>>>(yp, wpp, out, TC);
    }
}

// round 8
// speedup vs baseline: 4.1795x; 1.5425x over previous
#include <cuda_runtime.h>
#include <cuda_bf16.h>
#include <cuda_fp16.h>
#include <cstdint>
#include <math.h>

#define TB 2
#define TT 2048
#define TC 1024
#define TH 16
#define HD 64
#define BT (TB*TT)     // 4096 rows
#define KG 1024        // GEMM K (single-pass fp16)

// ---------------- scratch (allocation-free) ----------------
__device__ float g_qkv[(size_t)BT * 3 * TC];        // 48 MB
__device__ __half g_xh[(size_t)BT * TC];            // x fp16
__device__ __half g_yh[(size_t)BT * TC];            // y fp16
__device__ __half g_wah[(size_t)3 * TC * TC];       // W_attn^T fp16 [3072][1024]
__device__ __half g_wph[(size_t)TC * TC];           // W_proj^T fp16 [1024][1024]

__device__ __forceinline__ uint32_t smem_u32(const void* p) {
    uint32_t a;
    asm("{ .reg .u64 t; cvta.to.shared.u64 t, %1; cvt.u32.u64 %0, t; }" : "=r"(a) : "l"(p));
    return a;
}
__device__ __forceinline__ void ldmx4(uint32_t* r, uint32_t addr) {
    asm volatile("ldmatrix.sync.aligned.m8n8.x4.shared.b16 {%0,%1,%2,%3}, [%4];"
        : "=r"(r[0]), "=r"(r[1]), "=r"(r[2]), "=r"(r[3]) : "r"(addr));
}
// fp16 MMA (GEMMs)
__device__ __forceinline__ void mma16816h(float* c, const uint32_t* a, const uint32_t* b) {
    asm volatile("mma.sync.aligned.m16n8k16.row.col.f32.f16.f16.f32 "
        "{%0,%1,%2,%3}, {%4,%5,%6,%7}, {%8,%9}, {%0,%1,%2,%3};"
        : "+f"(c[0]), "+f"(c[1]), "+f"(c[2]), "+f"(c[3])
        : "r"(a[0]), "r"(a[1]), "r"(a[2]), "r"(a[3]), "r"(b[0]), "r"(b[1]));
}
// bf16 MMA (attention split path)
__device__ __forceinline__ void mma16816(float* c, const uint32_t* a, const uint32_t* b) {
    asm volatile("mma.sync.aligned.m16n8k16.row.col.f32.bf16.bf16.f32 "
        "{%0,%1,%2,%3}, {%4,%5,%6,%7}, {%8,%9}, {%0,%1,%2,%3};"
        : "+f"(c[0]), "+f"(c[1]), "+f"(c[2]), "+f"(c[3])
        : "r"(a[0]), "r"(a[1]), "r"(a[2]), "r"(a[3]), "r"(b[0]), "r"(b[1]));
}
__device__ __forceinline__ void cp_async16(uint32_t smem, const void* g) {
    asm volatile("cp.async.cg.shared.global [%0], [%1], 16;" :: "r"(smem), "l"(g));
}
#define CP_COMMIT() asm volatile("cp.async.commit_group;" ::: "memory")
#define CP_WAIT(n)  asm volatile("cp.async.wait_group %0;" :: "n"(n) : "memory")

// fp32 pair -> bf16 hi/lo packed b32 (attention precision path)
__device__ __forceinline__ void cvt_hl(float f0, float f1, uint32_t& h, uint32_t& l) {
    __nv_bfloat162 hb = __floats2bfloat162_rn(f0, f1);
    float2 hf = __bfloat1622float2(hb);
    __nv_bfloat162 lb = __floats2bfloat162_rn(f0 - hf.x, f1 - hf.y);
    h = *(uint32_t*)&hb;
    l = *(uint32_t*)&lb;
}

// ---------------- convert kernels ----------------
__global__ void conv_half(const float4* __restrict__ s, __half2* __restrict__ d, int n4) {
    int i = blockIdx.x * 256 + threadIdx.x;
    if (i >= n4) return;
    float4 f = s[i];
    d[2 * i]     = __floats2half2_rn(f.x, f.y);
    d[2 * i + 1] = __floats2half2_rn(f.z, f.w);
}

// W[K=1024][N] fp32 -> Wt[N][K] fp16
__global__ void conv_wt_half(const float* __restrict__ W, __half* __restrict__ d, int N) {
    __shared__ float t[32][33];
    const int k0 = blockIdx.y * 32, n0 = blockIdx.x * 32;
    const int tx = threadIdx.x, ty = threadIdx.y;
#pragma unroll
    for (int i = 0; i < 32; i += 8)
        t[ty + i][tx] = W[(size_t)(k0 + ty + i) * N + n0 + tx];
    __syncthreads();
#pragma unroll
    for (int i = 0; i < 32; i += 8)
        d[(size_t)(n0 + ty + i) * KG + k0 + tx] = __float2half(t[tx][ty + i]);
}

// ---------------- fp16 HMMA GEMM: 512 threads, 4-stage cp.async ----------------
#define BM 128
#define BN 256
#define BK 32
#define LDA 40                          // fp16/row (80B rows)
#define A_BYTES (BM * LDA * 2)
#define B_BYTES (BN * LDA * 2)
#define STG_STRIDE (A_BYTES + B_BYTES)
#define NSTG 4
#define GEMM_SMEM (NSTG * STG_STRIDE)   // 122880

__global__ __launch_bounds__(512, 1)
void gemm_hmma(const __half* __restrict__ A,
               const __half* __restrict__ B,
               float* __restrict__ C, int N) {
    extern __shared__ __half smb[];
    const uint32_t sbase = smem_u32(smb);
    const int tid = threadIdx.x, wid = tid >> 5, lane = tid & 31;
    const int m0 = blockIdx.y * BM, n0 = blockIdx.x * BN;
    const int wm0 = (wid >> 3) * 64;
    const int wn0 = (wid & 7) * 32;

    float acc[4][4][4];
#pragma unroll
    for (int f = 0; f < 4; f++)
#pragma unroll
        for (int j = 0; j < 4; j++)
#pragma unroll
            for (int e = 0; e < 4; e++) acc[f][j][e] = 0.f;

    const uint4* Ag = (const uint4*)A;
    const uint4* Bg = (const uint4*)B;
    const int KU = KG / 8;               // 128
    const int NST = KG / BK;             // 32

    const int arow = tid >> 2, ach = tid & 3;
    const int brow0 = tid >> 2, brow1 = (tid + 512) >> 2;

    auto issue = [&](int s) {
        const int kc = s * (BK / 8);
        const uint32_t As = sbase + (uint32_t)(s & (NSTG - 1)) * STG_STRIDE;
        const uint32_t Bs = As + A_BYTES;
        cp_async16(As + (uint32_t)((arow * LDA + ach * 8) * 2),
                   &Ag[(size_t)(m0 + arow) * KU + kc + ach]);
        cp_async16(Bs + (uint32_t)((brow0 * LDA + ach * 8) * 2),
                   &Bg[(size_t)(n0 + brow0) * KU + kc + ach]);
        cp_async16(Bs + (uint32_t)((brow1 * LDA + ach * 8) * 2),
                   &Bg[(size_t)(n0 + brow1) * KU + kc + ach]);
    };

    const int a_r = lane & 15, a_c = (lane >> 4) * 8;
    const int b_n = ((lane >> 4) & 1) * 8 + (lane & 7);
    const int b_k = ((lane >> 3) & 1) * 8;

#pragma unroll
    for (int s = 0; s < NSTG - 1; ++s) { issue(s); CP_COMMIT(); }

#pragma unroll 1
    for (int s = 0; s < NST; ++s) {
        CP_WAIT(NSTG - 2);
        __syncthreads();

        const uint32_t As0 = sbase + (uint32_t)(s & (NSTG - 1)) * STG_STRIDE;
        const uint32_t Bs0 = As0 + A_BYTES;

#pragma unroll
        for (int ks = 0; ks < 2; ++ks) {
            const int k0 = ks * 16;
            uint32_t afr[4][4], bfr[4][2];
#pragma unroll
            for (int f = 0; f < 4; f++)
                ldmx4(afr[f], As0 + (uint32_t)((wm0 + f * 16 + a_r) * 80 + (k0 + a_c) * 2));
#pragma unroll
            for (int p = 0; p < 2; p++) {
                uint32_t r[4];
                ldmx4(r, Bs0 + (uint32_t)((wn0 + p * 16 + b_n) * 80 + (k0 + b_k) * 2));
                bfr[2 * p][0] = r[0]; bfr[2 * p][1] = r[1];
                bfr[2 * p + 1][0] = r[2]; bfr[2 * p + 1][1] = r[3];
            }
#pragma unroll
            for (int f = 0; f < 4; f++)
#pragma unroll
                for (int j = 0; j < 4; j++)
                    mma16816h(acc[f][j], afr[f], bfr[j]);
        }

        if (s + NSTG - 1 < NST) issue(s + NSTG - 1);
        CP_COMMIT();
    }

    const int er = lane >> 2, ec = (lane & 3) * 2;
#pragma unroll
    for (int f = 0; f < 4; f++) {
        const int row = m0 + wm0 + f * 16 + er;
#pragma unroll
        for (int j = 0; j < 4; j++) {
            const int col = n0 + wn0 + j * 8 + ec;
            *(float2*)&C[(size_t)row * N + col]       = make_float2(acc[f][j][0], acc[f][j][1]);
            *(float2*)&C[(size_t)(row + 8) * N + col] = make_float2(acc[f][j][2], acc[f][j][3]);
        }
    }
}

// ---------------- tensor-core flash attention (split-bf16, epilogue -> fp16 y) ----
#define AP 72
#define ATT_SMEM (((2*128*AP) + (4*64*AP)) * 2 + 64*65*4)   // 90368 B

__global__ __launch_bounds__(256, 1)
void attn_mma(const float* __restrict__ qkv, __half* __restrict__ yh) {
    extern __shared__ char smc[];
    __nv_bfloat16* Qh = (__nv_bfloat16*)smc;
    __nv_bfloat16* Ql = Qh + 128 * AP;
    __nv_bfloat16* Kh = Ql + 128 * AP;
    __nv_bfloat16* Kl = Kh + 64 * AP;
    __nv_bfloat16* Vh = Kl + 64 * AP;
    __nv_bfloat16* Vl = Vh + 64 * AP;
    float* stg = (float*)(Vl + 64 * AP);

    const int qb = blockIdx.x, h = blockIdx.y, b = blockIdx.z;
    const int q0 = qb * 128;
    const int tid = threadIdx.x, wid = tid >> 5, lane = tid & 31;
    const int wq = wid * 16;
    const size_t rs = 3 * TC;
    const float* base = qkv + (size_t)b * TT * rs + h * HD;

    const int a_r = lane & 15, a_c = (lane >> 4) * 8;
    const int b_n = ((lane >> 4) & 1) * 8 + (lane & 7);
    const int b_k = ((lane >> 3) & 1) * 8;

#pragma unroll
    for (int p = 0; p < 8; ++p) {
        int i = tid + p * 256;
        int r = i >> 4, c4 = (i & 15) * 4;
        float4 f = *(const float4*)&base[(size_t)(q0 + r) * rs + c4];
        uint32_t h0, l0, h1, l1;
        cvt_hl(f.x, f.y, h0, l0);
        cvt_hl(f.z, f.w, h1, l1);
        *(uint32_t*)&Qh[r * AP + c4]     = h0; *(uint32_t*)&Qh[r * AP + c4 + 2] = h1;
        *(uint32_t*)&Ql[r * AP + c4]     = l0; *(uint32_t*)&Ql[r * AP + c4 + 2] = l1;
    }

    float mrow[2] = { -1e30f, -1e30f }, lrow[2] = { 0.f, 0.f };
    float oacc[8][4];
#pragma unroll
    for (int nb = 0; nb < 8; ++nb)
#pragma unroll
        for (int e = 0; e < 4; ++e) oacc[nb][e] = 0.f;

    const int nkt = qb * 2 + 2;
    for (int kt = 0; kt < nkt; ++kt) {
        const int k0 = kt * 64;
        __syncthreads();
#pragma unroll
        for (int p = 0; p < 4; ++p) {
            int i = tid + p * 256;
            int r = i >> 4, c4 = (i & 15) * 4;
            float4 f = *(const float4*)&base[(size_t)(k0 + r) * rs + TC + c4];
            uint32_t h0, l0, h1, l1;
            cvt_hl(f.x, f.y, h0, l0);
            cvt_hl(f.z, f.w, h1, l1);
            *(uint32_t*)&Kh[r * AP + c4]     = h0; *(uint32_t*)&Kh[r * AP + c4 + 2] = h1;
            *(uint32_t*)&Kl[r * AP + c4]     = l0; *(uint32_t*)&Kl[r * AP + c4 + 2] = l1;
        }
#pragma unroll
        for (int p = 0; p < 4; ++p) {
            int i = tid + p * 256;
            int r = i >> 4, c4 = (i & 15) * 4;
            float4 f = *(const float4*)&base[(size_t)(k0 + r) * rs + 2 * TC + c4];
            float* sp = &stg[r * 65 + c4];
            sp[0] = f.x; sp[1] = f.y; sp[2] = f.z; sp[3] = f.w;
        }
        __syncthreads();
#pragma unroll
        for (int p = 0; p < 16; ++p) {
            int i = tid + p * 256;
            int d = i >> 6, kc = i & 63;
            float f = stg[kc * 65 + d];
            __nv_bfloat16 hb = __float2bfloat16(f);
            Vh[d * AP + kc] = hb;
            Vl[d * AP + kc] = __float2bfloat16(f - __bfloat162float(hb));
        }
        __syncthreads();

        if (k0 > q0 + wq + 15) continue;

        float sacc[8][4];
#pragma unroll
        for (int nb = 0; nb < 8; ++nb)
#pragma unroll
            for (int e = 0; e < 4; ++e) sacc[nb][e] = 0.f;

        const uint32_t Qh0 = smem_u32(Qh), Ql0 = smem_u32(Ql);
        const uint32_t Kh0 = smem_u32(Kh), Kl0 = smem_u32(Kl);
#pragma unroll
        for (int ks = 0; ks < 4; ++ks) {
            const int kk = ks * 16;
            uint32_t qh[4], ql[4];
            ldmx4(qh, Qh0 + (uint32_t)(((wq + a_r) * AP + kk + a_c) * 2));
            ldmx4(ql, Ql0 + (uint32_t)(((wq + a_r) * AP + kk + a_c) * 2));
#pragma unroll
            for (int p = 0; p < 4; ++p) {
                uint32_t kh[4], kl[4];
                const uint32_t boff = (uint32_t)(((p * 16 + b_n) * AP + kk + b_k) * 2);
                ldmx4(kh, Kh0 + boff);
                ldmx4(kl, Kl0 + boff);
                mma16816(sacc[2 * p],     qh, &kh[0]);
                mma16816(sacc[2 * p + 1], qh, &kh[2]);
                mma16816(sacc[2 * p],     qh, &kl[0]);
                mma16816(sacc[2 * p + 1], qh, &kl[2]);
                mma16816(sacc[2 * p],     ql, &kh[0]);
                mma16816(sacc[2 * p + 1], ql, &kh[2]);
            }
        }

        const int grow0 = q0 + wq + (lane >> 2);
        const bool dmask = (k0 + 63) > (q0 + wq);
        float mloc0 = -1e30f, mloc1 = -1e30f;
#pragma unroll
        for (int nb = 0; nb < 8; ++nb) {
            const int col = k0 + nb * 8 + (lane & 3) * 2;
            float s0 = sacc[nb][0] * 0.125f, s1 = sacc[nb][1] * 0.125f;
            float s2 = sacc[nb][2] * 0.125f, s3 = sacc[nb][3] * 0.125f;
            if (dmask) {
                if (col     > grow0)     s0 = -1e30f;
                if (col + 1 > grow0)     s1 = -1e30f;
                if (col     > grow0 + 8) s2 = -1e30f;
                if (col + 1 > grow0 + 8) s3 = -1e30f;
            }
            sacc[nb][0] = s0; sacc[nb][1] = s1; sacc[nb][2] = s2; sacc[nb][3] = s3;
            mloc0 = fmaxf(mloc0, fmaxf(s0, s1));
            mloc1 = fmaxf(mloc1, fmaxf(s2, s3));
        }
        mloc0 = fmaxf(mloc0, __shfl_xor_sync(0xffffffffu, mloc0, 1));
        mloc0 = fmaxf(mloc0, __shfl_xor_sync(0xffffffffu, mloc0, 2));
        mloc1 = fmaxf(mloc1, __shfl_xor_sync(0xffffffffu, mloc1, 1));
        mloc1 = fmaxf(mloc1, __shfl_xor_sync(0xffffffffu, mloc1, 2));
        const float mn0 = fmaxf(mrow[0], mloc0);
        const float mn1 = fmaxf(mrow[1], mloc1);

        float sum0 = 0.f, sum1 = 0.f;
#pragma unroll
        for (int nb = 0; nb < 8; ++nb) {
            float e0 = __expf(sacc[nb][0] - mn0), e1 = __expf(sacc[nb][1] - mn0);
            float e2 = __expf(sacc[nb][2] - mn1), e3 = __expf(sacc[nb][3] - mn1);
            sacc[nb][0] = e0; sacc[nb][1] = e1; sacc[nb][2] = e2; sacc[nb][3] = e3;
            sum0 += e0 + e1; sum1 += e2 + e3;
        }
        sum0 += __shfl_xor_sync(0xffffffffu, sum0, 1);
        sum0 += __shfl_xor_sync(0xffffffffu, sum0, 2);
        sum1 += __shfl_xor_sync(0xffffffffu, sum1, 1);
        sum1 += __shfl_xor_sync(0xffffffffu, sum1, 2);

        const float sc0 = __expf(mrow[0] - mn0);
        const float sc1 = __expf(mrow[1] - mn1);
        lrow[0] = lrow[0] * sc0 + sum0;
        lrow[1] = lrow[1] * sc1 + sum1;
        mrow[0] = mn0; mrow[1] = mn1;
#pragma unroll
        for (int nb = 0; nb < 8; ++nb) {
            oacc[nb][0] *= sc0; oacc[nb][1] *= sc0;
            oacc[nb][2] *= sc1; oacc[nb][3] *= sc1;
        }

        uint32_t pfh[4][4], pfl[4][4];
#pragma unroll
        for (int c = 0; c < 4; ++c) {
            cvt_hl(sacc[2 * c][0],     sacc[2 * c][1],     pfh[c][0], pfl[c][0]);
            cvt_hl(sacc[2 * c][2],     sacc[2 * c][3],     pfh[c][1], pfl[c][1]);
            cvt_hl(sacc[2 * c + 1][0], sacc[2 * c + 1][1], pfh[c][2], pfl[c][2]);
            cvt_hl(sacc[2 * c + 1][2], sacc[2 * c + 1][3], pfh[c][3], pfl[c][3]);
        }

        const uint32_t Vh0 = smem_u32(Vh), Vl0 = smem_u32(Vl);
#pragma unroll
        for (int c = 0; c < 4; ++c) {
#pragma unroll
            for (int p = 0; p < 4; ++p) {
                uint32_t vh[4], vl[4];
                const uint32_t boff = (uint32_t)(((p * 16 + b_n) * AP + c * 16 + b_k) * 2);
                ldmx4(vh, Vh0 + boff);
                ldmx4(vl, Vl0 + boff);
                mma16816(oacc[2 * p],     pfh[c], &vh[0]);
                mma16816(oacc[2 * p + 1], pfh[c], &vh[2]);
                mma16816(oacc[2 * p],     pfl[c], &vh[0]);
                mma16816(oacc[2 * p + 1], pfl[c], &vh[2]);
                mma16816(oacc[2 * p],     pfh[c], &vl[0]);
                mma16816(oacc[2 * p + 1], pfh[c], &vl[2]);
            }
        }
    }

    // finalize: normalize + write y as fp16 [BT][1024]
    const float inv0 = 1.f / lrow[0], inv1 = 1.f / lrow[1];
    const int row0 = q0 + wq + (lane >> 2);
    const size_t rb0 = (size_t)(b * TT + row0) * TC + h * HD;
    const size_t rb1 = rb0 + (size_t)8 * TC;
#pragma unroll
    for (int nb = 0; nb < 8; ++nb) {
        const int d0 = nb * 8 + (lane & 3) * 2;
        __half2 v0 = __floats2half2_rn(oacc[nb][0] * inv0, oacc[nb][1] * inv0);
        __half2 v1 = __floats2half2_rn(oacc[nb][2] * inv1, oacc[nb][3] * inv1);
        *(__half2*)&yh[rb0 + d0] = v0;
        *(__half2*)&yh[rb1 + d0] = v1;
    }
}

// ---------------------------------------------------------------------------
extern "C" void kernel_launch(void* const* d_in, const int* in_sizes, int n_in,
                              void* d_out, int out_size) {
    const float* x  = (const float*)d_in[0];
    const float* Wa = (const float*)d_in[1];
    const float* Wp = (const float*)d_in[2];
    float* out = (float*)d_out;

    float* qkv;
    __half *xh, *yh, *wah, *wph;
    cudaGetSymbolAddress((void**)&qkv, g_qkv);
    cudaGetSymbolAddress((void**)&xh, g_xh);
    cudaGetSymbolAddress((void**)&yh, g_yh);
    cudaGetSymbolAddress((void**)&wah, g_wah);
    cudaGetSymbolAddress((void**)&wph, g_wph);

    cudaFuncSetAttribute(gemm_hmma, cudaFuncAttributeMaxDynamicSharedMemorySize, GEMM_SMEM);
    cudaFuncSetAttribute(attn_mma, cudaFuncAttributeMaxDynamicSharedMemorySize, ATT_SMEM);

    // x -> fp16
    {
        int n4 = BT * TC / 4;
        conv_half<<<(n4 + 255) / 256, 256>>>((const float4*)x, (__half2*)xh, n4);
    }
    // weights -> fp16 transposed
    {
        dim3 gw(3 * TC / 32, TC / 32);
        conv_wt_half<<<gw, dim3(32, 8)>>>(Wa, wah, 3 * TC);
        dim3 gp(TC / 32, TC / 32);
        conv_wt_half<<<gp, dim3(32, 8)>>>(Wp, wph, TC);
    }
    // qkv = x @ W_attn (fp16 single-pass)
    {
        dim3 g(3 * TC / BN, BT / BM);
        gemm_hmma<<<g, 512, GEMM_SMEM>>>(xh, wah, qkv, 3 * TC);
    }
    // attention (split-bf16) -> y fp16
    {
        dim3 ga(TT / 128, TH, TB);
        attn_mma<<<ga, 256, ATT_SMEM>>>(qkv, yh);
    }
    // out = y @ W_proj (fp16 single-pass)
    {
        dim3 g(TC / BN, BT / BM);
        gemm_hmma<<<g, 512, GEMM_SMEM>>>(yh, wph, out, TC);
    }
}

// round 9
// speedup vs baseline: 4.7233x; 1.1301x over previous
#include <cuda_runtime.h>
#include <cuda_bf16.h>
#include <cuda_fp16.h>
#include <cstdint>
#include <math.h>

#define TB 2
#define TT 2048
#define TC 1024
#define TH 16
#define HD 64
#define BT (TB*TT)     // 4096 rows
#define KG 1024        // GEMM K (single-pass fp16)

// ---------------- scratch (allocation-free) ----------------
__device__ float g_qkv[(size_t)BT * 3 * TC];        // 48 MB
__device__ __half g_xh[(size_t)BT * TC];
__device__ __half g_yh[(size_t)BT * TC];
__device__ __half g_wah[(size_t)3 * TC * TC];
__device__ __half g_wph[(size_t)TC * TC];
// attention operands, pre-split bf16 (per (b,h)): Q/K [t][d], V^T [d][t]
#define BH_ELEMS ((size_t)TB * TH * TT * HD)        // 4M elems, 8MB each
__device__ __nv_bfloat16 g_Qh[BH_ELEMS], g_Ql[BH_ELEMS];
__device__ __nv_bfloat16 g_Kh[BH_ELEMS], g_Kl[BH_ELEMS];
__device__ __nv_bfloat16 g_VTh[BH_ELEMS], g_VTl[BH_ELEMS];

__device__ __forceinline__ uint32_t smem_u32(const void* p) {
    uint32_t a;
    asm("{ .reg .u64 t; cvta.to.shared.u64 t, %1; cvt.u32.u64 %0, t; }" : "=r"(a) : "l"(p));
    return a;
}
__device__ __forceinline__ void ldmx4(uint32_t* r, uint32_t addr) {
    asm volatile("ldmatrix.sync.aligned.m8n8.x4.shared.b16 {%0,%1,%2,%3}, [%4];"
        : "=r"(r[0]), "=r"(r[1]), "=r"(r[2]), "=r"(r[3]) : "r"(addr));
}
__device__ __forceinline__ void mma16816h(float* c, const uint32_t* a, const uint32_t* b) {
    asm volatile("mma.sync.aligned.m16n8k16.row.col.f32.f16.f16.f32 "
        "{%0,%1,%2,%3}, {%4,%5,%6,%7}, {%8,%9}, {%0,%1,%2,%3};"
        : "+f"(c[0]), "+f"(c[1]), "+f"(c[2]), "+f"(c[3])
        : "r"(a[0]), "r"(a[1]), "r"(a[2]), "r"(a[3]), "r"(b[0]), "r"(b[1]));
}
__device__ __forceinline__ void mma16816(float* c, const uint32_t* a, const uint32_t* b) {
    asm volatile("mma.sync.aligned.m16n8k16.row.col.f32.bf16.bf16.f32 "
        "{%0,%1,%2,%3}, {%4,%5,%6,%7}, {%8,%9}, {%0,%1,%2,%3};"
        : "+f"(c[0]), "+f"(c[1]), "+f"(c[2]), "+f"(c[3])
        : "r"(a[0]), "r"(a[1]), "r"(a[2]), "r"(a[3]), "r"(b[0]), "r"(b[1]));
}
__device__ __forceinline__ void cp_async16(uint32_t smem, const void* g) {
    asm volatile("cp.async.cg.shared.global [%0], [%1], 16;" :: "r"(smem), "l"(g));
}
#define CP_COMMIT() asm volatile("cp.async.commit_group;" ::: "memory")
#define CP_WAIT(n)  asm volatile("cp.async.wait_group %0;" :: "n"(n) : "memory")

__device__ __forceinline__ void cvt_hl(float f0, float f1, uint32_t& h, uint32_t& l) {
    __nv_bfloat162 hb = __floats2bfloat162_rn(f0, f1);
    float2 hf = __bfloat1622float2(hb);
    __nv_bfloat162 lb = __floats2bfloat162_rn(f0 - hf.x, f1 - hf.y);
    h = *(uint32_t*)&hb;
    l = *(uint32_t*)&lb;
}

// ---------------- convert kernels ----------------
__global__ void conv_half(const float4* __restrict__ s, __half2* __restrict__ d, int n4) {
    int i = blockIdx.x * 256 + threadIdx.x;
    if (i >= n4) return;
    float4 f = s[i];
    d[2 * i]     = __floats2half2_rn(f.x, f.y);
    d[2 * i + 1] = __floats2half2_rn(f.z, f.w);
}

__global__ void conv_wt_half(const float* __restrict__ W, __half* __restrict__ d, int N) {
    __shared__ float t[32][33];
    const int k0 = blockIdx.y * 32, n0 = blockIdx.x * 32;
    const int tx = threadIdx.x, ty = threadIdx.y;
#pragma unroll
    for (int i = 0; i < 32; i += 8)
        t[ty + i][tx] = W[(size_t)(k0 + ty + i) * N + n0 + tx];
    __syncthreads();
#pragma unroll
    for (int i = 0; i < 32; i += 8)
        d[(size_t)(n0 + ty + i) * KG + k0 + tx] = __float2half(t[tx][ty + i]);
}

// qkv fp32 -> split bf16 Q/K row-major + V^T, per (b,h)
__global__ __launch_bounds__(256) void conv_qkv(const float* __restrict__ qkv) {
    __shared__ float stg[64 * 65];
    const int t0 = blockIdx.x * 64, h = blockIdx.y, b = blockIdx.z;
    const int tid = threadIdx.x;
    const float* base = qkv + (size_t)b * TT * (3 * TC) + h * HD;
    const size_t bh = (size_t)(b * TH + h);
    const size_t qkb = (bh * TT + t0) * HD;
#pragma unroll
    for (int p = 0; p < 4; ++p) {
        int i = tid + p * 256;
        int r = i >> 4, c4 = (i & 15) * 4;
        const float* rowp = base + (size_t)(t0 + r) * (3 * TC);
        float4 fq = *(const float4*)&rowp[c4];
        float4 fk = *(const float4*)&rowp[TC + c4];
        float4 fv = *(const float4*)&rowp[2 * TC + c4];
        uint32_t h0, l0, h1, l1;
        const size_t o = qkb + (size_t)r * HD + c4;
        cvt_hl(fq.x, fq.y, h0, l0); cvt_hl(fq.z, fq.w, h1, l1);
        *(uint32_t*)&g_Qh[o] = h0; *(uint32_t*)&g_Qh[o + 2] = h1;
        *(uint32_t*)&g_Ql[o] = l0; *(uint32_t*)&g_Ql[o + 2] = l1;
        cvt_hl(fk.x, fk.y, h0, l0); cvt_hl(fk.z, fk.w, h1, l1);
        *(uint32_t*)&g_Kh[o] = h0; *(uint32_t*)&g_Kh[o + 2] = h1;
        *(uint32_t*)&g_Kl[o] = l0; *(uint32_t*)&g_Kl[o + 2] = l1;
        float* sp = &stg[r * 65 + c4];
        sp[0] = fv.x; sp[1] = fv.y; sp[2] = fv.z; sp[3] = fv.w;
    }
    __syncthreads();
    const size_t vtb = bh * HD * TT + t0;
#pragma unroll
    for (int p = 0; p < 4; ++p) {
        int i = tid + p * 256;
        int d = i >> 4, t4 = (i & 15) * 4;
        float f0 = stg[(t4 + 0) * 65 + d], f1 = stg[(t4 + 1) * 65 + d];
        float f2 = stg[(t4 + 2) * 65 + d], f3 = stg[(t4 + 3) * 65 + d];
        uint32_t h0, l0, h1, l1;
        cvt_hl(f0, f1, h0, l0); cvt_hl(f2, f3, h1, l1);
        const size_t o = vtb + (size_t)d * TT + t4;
        *(uint32_t*)&g_VTh[o] = h0; *(uint32_t*)&g_VTh[o + 2] = h1;
        *(uint32_t*)&g_VTl[o] = l0; *(uint32_t*)&g_VTl[o + 2] = l1;
    }
}

// ---------------- fp16 HMMA GEMM (unchanged from R8, passing) ----------------
#define BM 128
#define BN 256
#define BK 32
#define LDA 40
#define A_BYTES (BM * LDA * 2)
#define B_BYTES (BN * LDA * 2)
#define STG_STRIDE (A_BYTES + B_BYTES)
#define NSTG 4
#define GEMM_SMEM (NSTG * STG_STRIDE)

__global__ __launch_bounds__(512, 1)
void gemm_hmma(const __half* __restrict__ A,
               const __half* __restrict__ B,
               float* __restrict__ C, int N) {
    extern __shared__ __half smb[];
    const uint32_t sbase = smem_u32(smb);
    const int tid = threadIdx.x, wid = tid >> 5, lane = tid & 31;
    const int m0 = blockIdx.y * BM, n0 = blockIdx.x * BN;
    const int wm0 = (wid >> 3) * 64;
    const int wn0 = (wid & 7) * 32;

    float acc[4][4][4];
#pragma unroll
    for (int f = 0; f < 4; f++)
#pragma unroll
        for (int j = 0; j < 4; j++)
#pragma unroll
            for (int e = 0; e < 4; e++) acc[f][j][e] = 0.f;

    const uint4* Ag = (const uint4*)A;
    const uint4* Bg = (const uint4*)B;
    const int KU = KG / 8;
    const int NST = KG / BK;

    const int arow = tid >> 2, ach = tid & 3;
    const int brow0 = tid >> 2, brow1 = (tid + 512) >> 2;

    auto issue = [&](int s) {
        const int kc = s * (BK / 8);
        const uint32_t As = sbase + (uint32_t)(s & (NSTG - 1)) * STG_STRIDE;
        const uint32_t Bs = As + A_BYTES;
        cp_async16(As + (uint32_t)((arow * LDA + ach * 8) * 2),
                   &Ag[(size_t)(m0 + arow) * KU + kc + ach]);
        cp_async16(Bs + (uint32_t)((brow0 * LDA + ach * 8) * 2),
                   &Bg[(size_t)(n0 + brow0) * KU + kc + ach]);
        cp_async16(Bs + (uint32_t)((brow1 * LDA + ach * 8) * 2),
                   &Bg[(size_t)(n0 + brow1) * KU + kc + ach]);
    };

    const int a_r = lane & 15, a_c = (lane >> 4) * 8;
    const int b_n = ((lane >> 4) & 1) * 8 + (lane & 7);
    const int b_k = ((lane >> 3) & 1) * 8;

#pragma unroll
    for (int s = 0; s < NSTG - 1; ++s) { issue(s); CP_COMMIT(); }

#pragma unroll 1
    for (int s = 0; s < NST; ++s) {
        CP_WAIT(NSTG - 2);
        __syncthreads();

        const uint32_t As0 = sbase + (uint32_t)(s & (NSTG - 1)) * STG_STRIDE;
        const uint32_t Bs0 = As0 + A_BYTES;

#pragma unroll
        for (int ks = 0; ks < 2; ++ks) {
            const int k0 = ks * 16;
            uint32_t afr[4][4], bfr[4][2];
#pragma unroll
            for (int f = 0; f < 4; f++)
                ldmx4(afr[f], As0 + (uint32_t)((wm0 + f * 16 + a_r) * 80 + (k0 + a_c) * 2));
#pragma unroll
            for (int p = 0; p < 2; p++) {
                uint32_t r[4];
                ldmx4(r, Bs0 + (uint32_t)((wn0 + p * 16 + b_n) * 80 + (k0 + b_k) * 2));
                bfr[2 * p][0] = r[0]; bfr[2 * p][1] = r[1];
                bfr[2 * p + 1][0] = r[2]; bfr[2 * p + 1][1] = r[3];
            }
#pragma unroll
            for (int f = 0; f < 4; f++)
#pragma unroll
                for (int j = 0; j < 4; j++)
                    mma16816h(acc[f][j], afr[f], bfr[j]);
        }

        if (s + NSTG - 1 < NST) issue(s + NSTG - 1);
        CP_COMMIT();
    }

    const int er = lane >> 2, ec = (lane & 3) * 2;
#pragma unroll
    for (int f = 0; f < 4; f++) {
        const int row = m0 + wm0 + f * 16 + er;
#pragma unroll
        for (int j = 0; j < 4; j++) {
            const int col = n0 + wn0 + j * 8 + ec;
            *(float2*)&C[(size_t)row * N + col]       = make_float2(acc[f][j][0], acc[f][j][1]);
            *(float2*)&C[(size_t)(row + 8) * N + col] = make_float2(acc[f][j][2], acc[f][j][3]);
        }
    }
}

// ---------------- flash attention: pre-split bf16 operands, 2-stage cp.async ----
#define AP 72
#define QBYTES (128 * AP * 2)          // 18432 per Q buffer
#define TILE_B (64 * AP * 2)           // 9216 per KV buffer
#define KV_STAGE (4 * TILE_B)          // 36864
#define ATT_SMEM (2 * QBYTES + 2 * KV_STAGE)  // 110592

__global__ __launch_bounds__(256, 1)
void attn_mma(__half* __restrict__ yh) {
    extern __shared__ char smc[];
    const uint32_t sb = smem_u32(smc);
    const uint32_t sQh = sb, sQl = sb + QBYTES;
    const uint32_t sKV = sb + 2 * QBYTES;

    const int qb = blockIdx.x, h = blockIdx.y, b = blockIdx.z;
    const int q0 = qb * 128;
    const int tid = threadIdx.x, wid = tid >> 5, lane = tid & 31;
    const int wq = wid * 16;
    const size_t bh = (size_t)(b * TH + h);

    const __nv_bfloat16* gQh = g_Qh + (bh * TT + q0) * HD;
    const __nv_bfloat16* gQl = g_Ql + (bh * TT + q0) * HD;
    const __nv_bfloat16* gKh = g_Kh + bh * TT * HD;
    const __nv_bfloat16* gKl = g_Kl + bh * TT * HD;
    const __nv_bfloat16* gVTh = g_VTh + bh * HD * TT;
    const __nv_bfloat16* gVTl = g_VTl + bh * HD * TT;

    const int a_r = lane & 15, a_c = (lane >> 4) * 8;
    const int b_n = ((lane >> 4) & 1) * 8 + (lane & 7);
    const int b_k = ((lane >> 3) & 1) * 8;

    // Q tiles: 128 rows x 8 chunks x {hi,lo} = 2048 chunks
#pragma unroll
    for (int p = 0; p < 8; ++p) {
        int i = tid + p * 256;
        int hl = i >> 10, rem = i & 1023, r = rem >> 3, ch = rem & 7;
        const __nv_bfloat16* src = (hl ? gQl : gQh) + (size_t)r * HD + ch * 8;
        cp_async16((hl ? sQl : sQh) + (uint32_t)(r * 144 + ch * 16), src);
    }

    auto issue_kv = [&](int kt) {
        const int k0 = kt * 64;
        const uint32_t stg = sKV + (uint32_t)(kt & 1) * KV_STAGE;
#pragma unroll
        for (int p = 0; p < 8; ++p) {
            int i = tid + p * 256;
            int buf = i >> 9, rem = i & 511, r = rem >> 3, ch = rem & 7;
            const __nv_bfloat16* src;
            if (buf == 0)      src = gKh  + (size_t)(k0 + r) * HD + ch * 8;
            else if (buf == 1) src = gKl  + (size_t)(k0 + r) * HD + ch * 8;
            else if (buf == 2) src = gVTh + (size_t)r * TT + k0 + ch * 8;
            else               src = gVTl + (size_t)r * TT + k0 + ch * 8;
            cp_async16(stg + (uint32_t)(buf * TILE_B + r * 144 + ch * 16), src);
        }
    };

    const int nkt = qb * 2 + 2;
    issue_kv(0);
    CP_COMMIT();   // group0 = Q + stage0

    float mrow[2] = { -1e30f, -1e30f }, lrow[2] = { 0.f, 0.f };
    float oacc[8][4];
#pragma unroll
    for (int nb = 0; nb < 8; ++nb)
#pragma unroll
        for (int e = 0; e < 4; ++e) oacc[nb][e] = 0.f;

    for (int kt = 0; kt < nkt; ++kt) {
        const int k0 = kt * 64;
        if (kt + 1 < nkt) { issue_kv(kt + 1); CP_COMMIT(); CP_WAIT(1); }
        else              { CP_WAIT(0); }
        __syncthreads();

        if (k0 <= q0 + wq + 15) {
            const uint32_t stg = sKV + (uint32_t)(kt & 1) * KV_STAGE;
            const uint32_t Kh0 = stg, Kl0 = stg + TILE_B;
            const uint32_t Vh0 = stg + 2 * TILE_B, Vl0 = stg + 3 * TILE_B;

            // ---- S = Q K^T (QhKh + QhKl + QlKh) ----
            float sacc[8][4];
#pragma unroll
            for (int nb = 0; nb < 8; ++nb)
#pragma unroll
                for (int e = 0; e < 4; ++e) sacc[nb][e] = 0.f;

#pragma unroll
            for (int ks = 0; ks < 4; ++ks) {
                const int kk = ks * 16;
                uint32_t qh[4], ql[4];
                const uint32_t qoff = (uint32_t)((wq + a_r) * 144 + (kk + a_c) * 2);
                ldmx4(qh, sQh + qoff);
                ldmx4(ql, sQl + qoff);
#pragma unroll
                for (int p = 0; p < 4; ++p) {
                    uint32_t kh[4], kl[4];
                    const uint32_t boff = (uint32_t)((p * 16 + b_n) * 144 + (kk + b_k) * 2);
                    ldmx4(kh, Kh0 + boff);
                    ldmx4(kl, Kl0 + boff);
                    mma16816(sacc[2 * p],     qh, &kh[0]);
                    mma16816(sacc[2 * p + 1], qh, &kh[2]);
                    mma16816(sacc[2 * p],     qh, &kl[0]);
                    mma16816(sacc[2 * p + 1], qh, &kl[2]);
                    mma16816(sacc[2 * p],     ql, &kh[0]);
                    mma16816(sacc[2 * p + 1], ql, &kh[2]);
                }
            }

            // ---- masked online softmax ----
            const int grow0 = q0 + wq + (lane >> 2);
            const bool dmask = (k0 + 63) > (q0 + wq);
            float mloc0 = -1e30f, mloc1 = -1e30f;
#pragma unroll
            for (int nb = 0; nb < 8; ++nb) {
                const int col = k0 + nb * 8 + (lane & 3) * 2;
                float s0 = sacc[nb][0] * 0.125f, s1 = sacc[nb][1] * 0.125f;
                float s2 = sacc[nb][2] * 0.125f, s3 = sacc[nb][3] * 0.125f;
                if (dmask) {
                    if (col     > grow0)     s0 = -1e30f;
                    if (col + 1 > grow0)     s1 = -1e30f;
                    if (col     > grow0 + 8) s2 = -1e30f;
                    if (col + 1 > grow0 + 8) s3 = -1e30f;
                }
                sacc[nb][0] = s0; sacc[nb][1] = s1; sacc[nb][2] = s2; sacc[nb][3] = s3;
                mloc0 = fmaxf(mloc0, fmaxf(s0, s1));
                mloc1 = fmaxf(mloc1, fmaxf(s2, s3));
            }
            mloc0 = fmaxf(mloc0, __shfl_xor_sync(0xffffffffu, mloc0, 1));
            mloc0 = fmaxf(mloc0, __shfl_xor_sync(0xffffffffu, mloc0, 2));
            mloc1 = fmaxf(mloc1, __shfl_xor_sync(0xffffffffu, mloc1, 1));
            mloc1 = fmaxf(mloc1, __shfl_xor_sync(0xffffffffu, mloc1, 2));
            const float mn0 = fmaxf(mrow[0], mloc0);
            const float mn1 = fmaxf(mrow[1], mloc1);

            float sum0 = 0.f, sum1 = 0.f;
#pragma unroll
            for (int nb = 0; nb < 8; ++nb) {
                float e0 = __expf(sacc[nb][0] - mn0), e1 = __expf(sacc[nb][1] - mn0);
                float e2 = __expf(sacc[nb][2] - mn1), e3 = __expf(sacc[nb][3] - mn1);
                sacc[nb][0] = e0; sacc[nb][1] = e1; sacc[nb][2] = e2; sacc[nb][3] = e3;
                sum0 += e0 + e1; sum1 += e2 + e3;
            }
            sum0 += __shfl_xor_sync(0xffffffffu, sum0, 1);
            sum0 += __shfl_xor_sync(0xffffffffu, sum0, 2);
            sum1 += __shfl_xor_sync(0xffffffffu, sum1, 1);
            sum1 += __shfl_xor_sync(0xffffffffu, sum1, 2);

            const float sc0 = __expf(mrow[0] - mn0);
            const float sc1 = __expf(mrow[1] - mn1);
            lrow[0] = lrow[0] * sc0 + sum0;
            lrow[1] = lrow[1] * sc1 + sum1;
            mrow[0] = mn0; mrow[1] = mn1;
#pragma unroll
            for (int nb = 0; nb < 8; ++nb) {
                oacc[nb][0] *= sc0; oacc[nb][1] *= sc0;
                oacc[nb][2] *= sc1; oacc[nb][3] *= sc1;
            }

            // ---- P -> bf16 hi/lo A-frags ----
            uint32_t pfh[4][4], pfl[4][4];
#pragma unroll
            for (int c = 0; c < 4; ++c) {
                cvt_hl(sacc[2 * c][0],     sacc[2 * c][1],     pfh[c][0], pfl[c][0]);
                cvt_hl(sacc[2 * c][2],     sacc[2 * c][3],     pfh[c][1], pfl[c][1]);
                cvt_hl(sacc[2 * c + 1][0], sacc[2 * c + 1][1], pfh[c][2], pfl[c][2]);
                cvt_hl(sacc[2 * c + 1][2], sacc[2 * c + 1][3], pfh[c][3], pfl[c][3]);
            }

            // ---- O += P V (PhVh + PlVh + PhVl) ----
#pragma unroll
            for (int c = 0; c < 4; ++c) {
#pragma unroll
                for (int p = 0; p < 4; ++p) {
                    uint32_t vh[4], vl[4];
                    const uint32_t boff = (uint32_t)((p * 16 + b_n) * 144 + (c * 16 + b_k) * 2);
                    ldmx4(vh, Vh0 + boff);
                    ldmx4(vl, Vl0 + boff);
                    mma16816(oacc[2 * p],     pfh[c], &vh[0]);
                    mma16816(oacc[2 * p + 1], pfh[c], &vh[2]);
                    mma16816(oacc[2 * p],     pfl[c], &vh[0]);
                    mma16816(oacc[2 * p + 1], pfl[c], &vh[2]);
                    mma16816(oacc[2 * p],     pfh[c], &vl[0]);
                    mma16816(oacc[2 * p + 1], pfh[c], &vl[2]);
                }
            }
        }
        __syncthreads();   // all reads of this stage done before it is re-filled
    }

    const float inv0 = 1.f / lrow[0], inv1 = 1.f / lrow[1];
    const int row0 = q0 + wq + (lane >> 2);
    const size_t rb0 = (size_t)(b * TT + row0) * TC + h * HD;
    const size_t rb1 = rb0 + (size_t)8 * TC;
#pragma unroll
    for (int nb = 0; nb < 8; ++nb) {
        const int d0 = nb * 8 + (lane & 3) * 2;
        __half2 v0 = __floats2half2_rn(oacc[nb][0] * inv0, oacc[nb][1] * inv0);
        __half2 v1 = __floats2half2_rn(oacc[nb][2] * inv1, oacc[nb][3] * inv1);
        *(__half2*)&yh[rb0 + d0] = v0;
        *(__half2*)&yh[rb1 + d0] = v1;
    }
}

// ---------------------------------------------------------------------------
extern "C" void kernel_launch(void* const* d_in, const int* in_sizes, int n_in,
                              void* d_out, int out_size) {
    const float* x  = (const float*)d_in[0];
    const float* Wa = (const float*)d_in[1];
    const float* Wp = (const float*)d_in[2];
    float* out = (float*)d_out;

    float* qkv;
    __half *xh, *yh, *wah, *wph;
    cudaGetSymbolAddress((void**)&qkv, g_qkv);
    cudaGetSymbolAddress((void**)&xh, g_xh);
    cudaGetSymbolAddress((void**)&yh, g_yh);
    cudaGetSymbolAddress((void**)&wah, g_wah);
    cudaGetSymbolAddress((void**)&wph, g_wph);

    cudaFuncSetAttribute(gemm_hmma, cudaFuncAttributeMaxDynamicSharedMemorySize, GEMM_SMEM);
    cudaFuncSetAttribute(attn_mma, cudaFuncAttributeMaxDynamicSharedMemorySize, ATT_SMEM);

    // x -> fp16
    {
        int n4 = BT * TC / 4;
        conv_half<<<(n4 + 255) / 256, 256>>>((const float4*)x, (__half2*)xh, n4);
    }
    // weights -> fp16 transposed
    {
        dim3 gw(3 * TC / 32, TC / 32);
        conv_wt_half<<<gw, dim3(32, 8)>>>(Wa, wah, 3 * TC);
        dim3 gp(TC / 32, TC / 32);
        conv_wt_half<<<gp, dim3(32, 8)>>>(Wp, wph, TC);
    }
    // qkv = x @ W_attn
    {
        dim3 g(3 * TC / BN, BT / BM);
        gemm_hmma<<<g, 512, GEMM_SMEM>>>(xh, wah, qkv, 3 * TC);
    }
    // split qkv -> bf16 hi/lo attention operands (V pre-transposed)
    {
        dim3 gc(TT / 64, TH, TB);
        conv_qkv<<<gc, 256>>>(qkv);
    }
    // attention -> y fp16
    {
        dim3 ga(TT / 128, TH, TB);
        attn_mma<<<ga, 256, ATT_SMEM>>>(yh);
    }
    // out = y @ W_proj
    {
        dim3 g(TC / BN, BT / BM);
        gemm_hmma<<<g, 512, GEMM_SMEM>>>(yh, wph, out, TC);
    }
}

// round 10
// speedup vs baseline: 4.7558x; 1.0069x over previous
#include <cuda_runtime.h>
#include <cuda_bf16.h>
#include <cuda_fp16.h>
#include <cstdint>
#include <math.h>

#define TB 2
#define TT 2048
#define TC 1024
#define TH 16
#define HD 64
#define BT (TB*TT)     // 4096 rows
#define KG 1024        // GEMM K

// ---------------- scratch (allocation-free) ----------------
__device__ __half g_xh[(size_t)BT * TC];
__device__ __half g_yh[(size_t)BT * TC];
__device__ __half g_wah[(size_t)3 * TC * TC];
__device__ __half g_wph[(size_t)TC * TC];
// attention operands, pre-split bf16 (per (b,h)): Q/K [t][d], V^T [d][t]
#define BH_ELEMS ((size_t)TB * TH * TT * HD)
__device__ __nv_bfloat16 g_Qh[BH_ELEMS], g_Ql[BH_ELEMS];
__device__ __nv_bfloat16 g_Kh[BH_ELEMS], g_Kl[BH_ELEMS];
__device__ __nv_bfloat16 g_VTh[BH_ELEMS], g_VTl[BH_ELEMS];

__device__ __forceinline__ uint32_t smem_u32(const void* p) {
    uint32_t a;
    asm("{ .reg .u64 t; cvta.to.shared.u64 t, %1; cvt.u32.u64 %0, t; }" : "=r"(a) : "l"(p));
    return a;
}
__device__ __forceinline__ void ldmx4(uint32_t* r, uint32_t addr) {
    asm volatile("ldmatrix.sync.aligned.m8n8.x4.shared.b16 {%0,%1,%2,%3}, [%4];"
        : "=r"(r[0]), "=r"(r[1]), "=r"(r[2]), "=r"(r[3]) : "r"(addr));
}
__device__ __forceinline__ void mma16816h(float* c, const uint32_t* a, const uint32_t* b) {
    asm volatile("mma.sync.aligned.m16n8k16.row.col.f32.f16.f16.f32 "
        "{%0,%1,%2,%3}, {%4,%5,%6,%7}, {%8,%9}, {%0,%1,%2,%3};"
        : "+f"(c[0]), "+f"(c[1]), "+f"(c[2]), "+f"(c[3])
        : "r"(a[0]), "r"(a[1]), "r"(a[2]), "r"(a[3]), "r"(b[0]), "r"(b[1]));
}
__device__ __forceinline__ void mma16816(float* c, const uint32_t* a, const uint32_t* b) {
    asm volatile("mma.sync.aligned.m16n8k16.row.col.f32.bf16.bf16.f32 "
        "{%0,%1,%2,%3}, {%4,%5,%6,%7}, {%8,%9}, {%0,%1,%2,%3};"
        : "+f"(c[0]), "+f"(c[1]), "+f"(c[2]), "+f"(c[3])
        : "r"(a[0]), "r"(a[1]), "r"(a[2]), "r"(a[3]), "r"(b[0]), "r"(b[1]));
}
__device__ __forceinline__ void cp_async16(uint32_t smem, const void* g) {
    asm volatile("cp.async.cg.shared.global [%0], [%1], 16;" :: "r"(smem), "l"(g));
}
#define CP_COMMIT() asm volatile("cp.async.commit_group;" ::: "memory")
#define CP_WAIT(n)  asm volatile("cp.async.wait_group %0;" :: "n"(n) : "memory")

__device__ __forceinline__ void cvt_hl(float f0, float f1, uint32_t& h, uint32_t& l) {
    __nv_bfloat162 hb = __floats2bfloat162_rn(f0, f1);
    float2 hf = __bfloat1622float2(hb);
    __nv_bfloat162 lb = __floats2bfloat162_rn(f0 - hf.x, f1 - hf.y);
    h = *(uint32_t*)&hb;
    l = *(uint32_t*)&lb;
}

// ---------------- convert kernels ----------------
__global__ void conv_half(const float4* __restrict__ s, __half2* __restrict__ d, int n4) {
    int i = blockIdx.x * 256 + threadIdx.x;
    if (i >= n4) return;
    float4 f = s[i];
    d[2 * i]     = __floats2half2_rn(f.x, f.y);
    d[2 * i + 1] = __floats2half2_rn(f.z, f.w);
}

__global__ void conv_wt_half(const float* __restrict__ W, __half* __restrict__ d, int N) {
    __shared__ float t[32][33];
    const int k0 = blockIdx.y * 32, n0 = blockIdx.x * 32;
    const int tx = threadIdx.x, ty = threadIdx.y;
#pragma unroll
    for (int i = 0; i < 32; i += 8)
        t[ty + i][tx] = W[(size_t)(k0 + ty + i) * N + n0 + tx];
    __syncthreads();
#pragma unroll
    for (int i = 0; i < 32; i += 8)
        d[(size_t)(n0 + ty + i) * KG + k0 + tx] = __float2half(t[tx][ty + i]);
}

// ---------------- fp16 HMMA GEMM, templated epilogue ----------------
// MODE 0: write fp32 C.   MODE 1: split-qkv epilogue -> g_Qh/Ql/Kh/Kl/VTh/VTl.
#define BM 128
#define BN 256
#define BK 32
#define LDA 40
#define A_BYTES (BM * LDA * 2)
#define B_BYTES (BN * LDA * 2)
#define STG_STRIDE (A_BYTES + B_BYTES)
#define NSTG 4
#define GEMM_SMEM (NSTG * STG_STRIDE)

template <int MODE>
__global__ __launch_bounds__(512, 1)
void gemm_hmma(const __half* __restrict__ A,
               const __half* __restrict__ B,
               float* __restrict__ C, int N) {
    extern __shared__ __half smb[];
    const uint32_t sbase = smem_u32(smb);
    const int tid = threadIdx.x, wid = tid >> 5, lane = tid & 31;
    const int m0 = blockIdx.y * BM, n0 = blockIdx.x * BN;
    const int wm0 = (wid >> 3) * 64;
    const int wn0 = (wid & 7) * 32;

    float acc[4][4][4];
#pragma unroll
    for (int f = 0; f < 4; f++)
#pragma unroll
        for (int j = 0; j < 4; j++)
#pragma unroll
            for (int e = 0; e < 4; e++) acc[f][j][e] = 0.f;

    const uint4* Ag = (const uint4*)A;
    const uint4* Bg = (const uint4*)B;
    const int KU = KG / 8;
    const int NST = KG / BK;

    const int arow = tid >> 2, ach = tid & 3;
    const int brow0 = tid >> 2, brow1 = (tid + 512) >> 2;

    auto issue = [&](int s) {
        const int kc = s * (BK / 8);
        const uint32_t As = sbase + (uint32_t)(s & (NSTG - 1)) * STG_STRIDE;
        const uint32_t Bs = As + A_BYTES;
        cp_async16(As + (uint32_t)((arow * LDA + ach * 8) * 2),
                   &Ag[(size_t)(m0 + arow) * KU + kc + ach]);
        cp_async16(Bs + (uint32_t)((brow0 * LDA + ach * 8) * 2),
                   &Bg[(size_t)(n0 + brow0) * KU + kc + ach]);
        cp_async16(Bs + (uint32_t)((brow1 * LDA + ach * 8) * 2),
                   &Bg[(size_t)(n0 + brow1) * KU + kc + ach]);
    };

    const int a_r = lane & 15, a_c = (lane >> 4) * 8;
    const int b_n = ((lane >> 4) & 1) * 8 + (lane & 7);
    const int b_k = ((lane >> 3) & 1) * 8;

#pragma unroll
    for (int s = 0; s < NSTG - 1; ++s) { issue(s); CP_COMMIT(); }

#pragma unroll 1
    for (int s = 0; s < NST; ++s) {
        CP_WAIT(NSTG - 2);
        __syncthreads();

        const uint32_t As0 = sbase + (uint32_t)(s & (NSTG - 1)) * STG_STRIDE;
        const uint32_t Bs0 = As0 + A_BYTES;

#pragma unroll
        for (int ks = 0; ks < 2; ++ks) {
            const int k0 = ks * 16;
            uint32_t afr[4][4], bfr[4][2];
#pragma unroll
            for (int f = 0; f < 4; f++)
                ldmx4(afr[f], As0 + (uint32_t)((wm0 + f * 16 + a_r) * 80 + (k0 + a_c) * 2));
#pragma unroll
            for (int p = 0; p < 2; p++) {
                uint32_t r[4];
                ldmx4(r, Bs0 + (uint32_t)((wn0 + p * 16 + b_n) * 80 + (k0 + b_k) * 2));
                bfr[2 * p][0] = r[0]; bfr[2 * p][1] = r[1];
                bfr[2 * p + 1][0] = r[2]; bfr[2 * p + 1][1] = r[3];
            }
#pragma unroll
            for (int f = 0; f < 4; f++)
#pragma unroll
                for (int j = 0; j < 4; j++)
                    mma16816h(acc[f][j], afr[f], bfr[j]);
        }

        if (s + NSTG - 1 < NST) issue(s + NSTG - 1);
        CP_COMMIT();
    }

    const int er = lane >> 2, ec = (lane & 3) * 2;
    if (MODE == 0) {
#pragma unroll
        for (int f = 0; f < 4; f++) {
            const int row = m0 + wm0 + f * 16 + er;
#pragma unroll
            for (int j = 0; j < 4; j++) {
                const int col = n0 + wn0 + j * 8 + ec;
                *(float2*)&C[(size_t)row * N + col]       = make_float2(acc[f][j][0], acc[f][j][1]);
                *(float2*)&C[(size_t)(row + 8) * N + col] = make_float2(acc[f][j][2], acc[f][j][3]);
            }
        }
    } else {
        // split-qkv epilogue: rows are (b*2048 + t); cols map to {Q,K,V} x head x d
#pragma unroll
        for (int f = 0; f < 4; f++) {
            const int row = m0 + wm0 + f * 16 + er;
            const int b = row >> 11, t = row & 2047;   // row+8 stays in same b (128 | 2048)
#pragma unroll
            for (int j = 0; j < 4; j++) {
                const int col = n0 + wn0 + j * 8 + ec;  // uniform sec/head across the pair
                const int sec = col >> 10;
                const int hh = (col >> 6) & 15;
                const int d = col & 63;
                const int bh = b * TH + hh;
                if (sec < 2) {
                    uint32_t h0, l0, h1, l1;
                    cvt_hl(acc[f][j][0], acc[f][j][1], h0, l0);   // row t,   d..d+1
                    cvt_hl(acc[f][j][2], acc[f][j][3], h1, l1);   // row t+8, d..d+1
                    const size_t o = ((size_t)bh * TT + t) * HD + d;
                    if (sec == 0) {
                        *(uint32_t*)&g_Qh[o] = h0;           *(uint32_t*)&g_Ql[o] = l0;
                        *(uint32_t*)&g_Qh[o + 8 * HD] = h1;  *(uint32_t*)&g_Ql[o + 8 * HD] = l1;
                    } else {
                        *(uint32_t*)&g_Kh[o] = h0;           *(uint32_t*)&g_Kl[o] = l0;
                        *(uint32_t*)&g_Kh[o + 8 * HD] = h1;  *(uint32_t*)&g_Kl[o + 8 * HD] = l1;
                    }
                } else {
                    // V transposed: VT[d][t], scalar bf16 stores
                    const size_t o = ((size_t)bh * HD + d) * TT + t;
                    float v;
                    __nv_bfloat16 hb;
                    v = acc[f][j][0]; hb = __float2bfloat16(v);
                    g_VTh[o] = hb;            g_VTl[o] = __float2bfloat16(v - __bfloat162float(hb));
                    v = acc[f][j][2]; hb = __float2bfloat16(v);
                    g_VTh[o + 8] = hb;        g_VTl[o + 8] = __float2bfloat16(v - __bfloat162float(hb));
                    v = acc[f][j][1]; hb = __float2bfloat16(v);
                    g_VTh[o + TT] = hb;       g_VTl[o + TT] = __float2bfloat16(v - __bfloat162float(hb));
                    v = acc[f][j][3]; hb = __float2bfloat16(v);
                    g_VTh[o + TT + 8] = hb;   g_VTl[o + TT + 8] = __float2bfloat16(v - __bfloat162float(hb));
                }
            }
        }
    }
}

// ---------------- flash attention (unchanged from R9, passing) ----------------
#define AP 72
#define QBYTES (128 * AP * 2)
#define TILE_B (64 * AP * 2)
#define KV_STAGE (4 * TILE_B)
#define ATT_SMEM (2 * QBYTES + 2 * KV_STAGE)  // 110592

__global__ __launch_bounds__(256, 1)
void attn_mma(__half* __restrict__ yh) {
    extern __shared__ char smc[];
    const uint32_t sb = smem_u32(smc);
    const uint32_t sQh = sb, sQl = sb + QBYTES;
    const uint32_t sKV = sb + 2 * QBYTES;

    const int qb = blockIdx.x, h = blockIdx.y, b = blockIdx.z;
    const int q0 = qb * 128;
    const int tid = threadIdx.x, wid = tid >> 5, lane = tid & 31;
    const int wq = wid * 16;
    const size_t bh = (size_t)(b * TH + h);

    const __nv_bfloat16* gQh = g_Qh + (bh * TT + q0) * HD;
    const __nv_bfloat16* gQl = g_Ql + (bh * TT + q0) * HD;
    const __nv_bfloat16* gKh = g_Kh + bh * TT * HD;
    const __nv_bfloat16* gKl = g_Kl + bh * TT * HD;
    const __nv_bfloat16* gVTh = g_VTh + bh * HD * TT;
    const __nv_bfloat16* gVTl = g_VTl + bh * HD * TT;

    const int a_r = lane & 15, a_c = (lane >> 4) * 8;
    const int b_n = ((lane >> 4) & 1) * 8 + (lane & 7);
    const int b_k = ((lane >> 3) & 1) * 8;

#pragma unroll
    for (int p = 0; p < 8; ++p) {
        int i = tid + p * 256;
        int hl = i >> 10, rem = i & 1023, r = rem >> 3, ch = rem & 7;
        const __nv_bfloat16* src = (hl ? gQl : gQh) + (size_t)r * HD + ch * 8;
        cp_async16((hl ? sQl : sQh) + (uint32_t)(r * 144 + ch * 16), src);
    }

    auto issue_kv = [&](int kt) {
        const int k0 = kt * 64;
        const uint32_t stg = sKV + (uint32_t)(kt & 1) * KV_STAGE;
#pragma unroll
        for (int p = 0; p < 8; ++p) {
            int i = tid + p * 256;
            int buf = i >> 9, rem = i & 511, r = rem >> 3, ch = rem & 7;
            const __nv_bfloat16* src;
            if (buf == 0)      src = gKh  + (size_t)(k0 + r) * HD + ch * 8;
            else if (buf == 1) src = gKl  + (size_t)(k0 + r) * HD + ch * 8;
            else if (buf == 2) src = gVTh + (size_t)r * TT + k0 + ch * 8;
            else               src = gVTl + (size_t)r * TT + k0 + ch * 8;
            cp_async16(stg + (uint32_t)(buf * TILE_B + r * 144 + ch * 16), src);
        }
    };

    const int nkt = qb * 2 + 2;
    issue_kv(0);
    CP_COMMIT();

    float mrow[2] = { -1e30f, -1e30f }, lrow[2] = { 0.f, 0.f };
    float oacc[8][4];
#pragma unroll
    for (int nb = 0; nb < 8; ++nb)
#pragma unroll
        for (int e = 0; e < 4; ++e) oacc[nb][e] = 0.f;

    for (int kt = 0; kt < nkt; ++kt) {
        const int k0 = kt * 64;
        if (kt + 1 < nkt) { issue_kv(kt + 1); CP_COMMIT(); CP_WAIT(1); }
        else              { CP_WAIT(0); }
        __syncthreads();

        if (k0 <= q0 + wq + 15) {
            const uint32_t stg = sKV + (uint32_t)(kt & 1) * KV_STAGE;
            const uint32_t Kh0 = stg, Kl0 = stg + TILE_B;
            const uint32_t Vh0 = stg + 2 * TILE_B, Vl0 = stg + 3 * TILE_B;

            float sacc[8][4];
#pragma unroll
            for (int nb = 0; nb < 8; ++nb)
#pragma unroll
                for (int e = 0; e < 4; ++e) sacc[nb][e] = 0.f;

#pragma unroll
            for (int ks = 0; ks < 4; ++ks) {
                const int kk = ks * 16;
                uint32_t qh[4], ql[4];
                const uint32_t qoff = (uint32_t)((wq + a_r) * 144 + (kk + a_c) * 2);
                ldmx4(qh, sQh + qoff);
                ldmx4(ql, sQl + qoff);
#pragma unroll
                for (int p = 0; p < 4; ++p) {
                    uint32_t kh[4], kl[4];
                    const uint32_t boff = (uint32_t)((p * 16 + b_n) * 144 + (kk + b_k) * 2);
                    ldmx4(kh, Kh0 + boff);
                    ldmx4(kl, Kl0 + boff);
                    mma16816(sacc[2 * p],     qh, &kh[0]);
                    mma16816(sacc[2 * p + 1], qh, &kh[2]);
                    mma16816(sacc[2 * p],     qh, &kl[0]);
                    mma16816(sacc[2 * p + 1], qh, &kl[2]);
                    mma16816(sacc[2 * p],     ql, &kh[0]);
                    mma16816(sacc[2 * p + 1], ql, &kh[2]);
                }
            }

            const int grow0 = q0 + wq + (lane >> 2);
            const bool dmask = (k0 + 63) > (q0 + wq);
            float mloc0 = -1e30f, mloc1 = -1e30f;
#pragma unroll
            for (int nb = 0; nb < 8; ++nb) {
                const int col = k0 + nb * 8 + (lane & 3) * 2;
                float s0 = sacc[nb][0] * 0.125f, s1 = sacc[nb][1] * 0.125f;
                float s2 = sacc[nb][2] * 0.125f, s3 = sacc[nb][3] * 0.125f;
                if (dmask) {
                    if (col     > grow0)     s0 = -1e30f;
                    if (col + 1 > grow0)     s1 = -1e30f;
                    if (col     > grow0 + 8) s2 = -1e30f;
                    if (col + 1 > grow0 + 8) s3 = -1e30f;
                }
                sacc[nb][0] = s0; sacc[nb][1] = s1; sacc[nb][2] = s2; sacc[nb][3] = s3;
                mloc0 = fmaxf(mloc0, fmaxf(s0, s1));
                mloc1 = fmaxf(mloc1, fmaxf(s2, s3));
            }
            mloc0 = fmaxf(mloc0, __shfl_xor_sync(0xffffffffu, mloc0, 1));
            mloc0 = fmaxf(mloc0, __shfl_xor_sync(0xffffffffu, mloc0, 2));
            mloc1 = fmaxf(mloc1, __shfl_xor_sync(0xffffffffu, mloc1, 1));
            mloc1 = fmaxf(mloc1, __shfl_xor_sync(0xffffffffu, mloc1, 2));
            const float mn0 = fmaxf(mrow[0], mloc0);
            const float mn1 = fmaxf(mrow[1], mloc1);

            float sum0 = 0.f, sum1 = 0.f;
#pragma unroll
            for (int nb = 0; nb < 8; ++nb) {
                float e0 = __expf(sacc[nb][0] - mn0), e1 = __expf(sacc[nb][1] - mn0);
                float e2 = __expf(sacc[nb][2] - mn1), e3 = __expf(sacc[nb][3] - mn1);
                sacc[nb][0] = e0; sacc[nb][1] = e1; sacc[nb][2] = e2; sacc[nb][3] = e3;
                sum0 += e0 + e1; sum1 += e2 + e3;
            }
            sum0 += __shfl_xor_sync(0xffffffffu, sum0, 1);
            sum0 += __shfl_xor_sync(0xffffffffu, sum0, 2);
            sum1 += __shfl_xor_sync(0xffffffffu, sum1, 1);
            sum1 += __shfl_xor_sync(0xffffffffu, sum1, 2);

            const float sc0 = __expf(mrow[0] - mn0);
            const float sc1 = __expf(mrow[1] - mn1);
            lrow[0] = lrow[0] * sc0 + sum0;
            lrow[1] = lrow[1] * sc1 + sum1;
            mrow[0] = mn0; mrow[1] = mn1;
#pragma unroll
            for (int nb = 0; nb < 8; ++nb) {
                oacc[nb][0] *= sc0; oacc[nb][1] *= sc0;
                oacc[nb][2] *= sc1; oacc[nb][3] *= sc1;
            }

            uint32_t pfh[4][4], pfl[4][4];
#pragma unroll
            for (int c = 0; c < 4; ++c) {
                cvt_hl(sacc[2 * c][0],     sacc[2 * c][1],     pfh[c][0], pfl[c][0]);
                cvt_hl(sacc[2 * c][2],     sacc[2 * c][3],     pfh[c][1], pfl[c][1]);
                cvt_hl(sacc[2 * c + 1][0], sacc[2 * c + 1][1], pfh[c][2], pfl[c][2]);
                cvt_hl(sacc[2 * c + 1][2], sacc[2 * c + 1][3], pfh[c][3], pfl[c][3]);
            }

#pragma unroll
            for (int c = 0; c < 4; ++c) {
#pragma unroll
                for (int p = 0; p < 4; ++p) {
                    uint32_t vh[4], vl[4];
                    const uint32_t boff = (uint32_t)((p * 16 + b_n) * 144 + (c * 16 + b_k) * 2);
                    ldmx4(vh, Vh0 + boff);
                    ldmx4(vl, Vl0 + boff);
                    mma16816(oacc[2 * p],     pfh[c], &vh[0]);
                    mma16816(oacc[2 * p + 1], pfh[c], &vh[2]);
                    mma16816(oacc[2 * p],     pfl[c], &vh[0]);
                    mma16816(oacc[2 * p + 1], pfl[c], &vh[2]);
                    mma16816(oacc[2 * p],     pfh[c], &vl[0]);
                    mma16816(oacc[2 * p + 1], pfh[c], &vl[2]);
                }
            }
        }
        __syncthreads();
    }

    const float inv0 = 1.f / lrow[0], inv1 = 1.f / lrow[1];
    const int row0 = q0 + wq + (lane >> 2);
    const size_t rb0 = (size_t)(b * TT + row0) * TC + h * HD;
    const size_t rb1 = rb0 + (size_t)8 * TC;
#pragma unroll
    for (int nb = 0; nb < 8; ++nb) {
        const int d0 = nb * 8 + (lane & 3) * 2;
        __half2 v0 = __floats2half2_rn(oacc[nb][0] * inv0, oacc[nb][1] * inv0);
        __half2 v1 = __floats2half2_rn(oacc[nb][2] * inv1, oacc[nb][3] * inv1);
        *(__half2*)&yh[rb0 + d0] = v0;
        *(__half2*)&yh[rb1 + d0] = v1;
    }
}

// ---------------------------------------------------------------------------
extern "C" void kernel_launch(void* const* d_in, const int* in_sizes, int n_in,
                              void* d_out, int out_size) {
    const float* x  = (const float*)d_in[0];
    const float* Wa = (const float*)d_in[1];
    const float* Wp = (const float*)d_in[2];
    float* out = (float*)d_out;

    __half *xh, *yh, *wah, *wph;
    cudaGetSymbolAddress((void**)&xh, g_xh);
    cudaGetSymbolAddress((void**)&yh, g_yh);
    cudaGetSymbolAddress((void**)&wah, g_wah);
    cudaGetSymbolAddress((void**)&wph, g_wph);

    cudaFuncSetAttribute(gemm_hmma<0>, cudaFuncAttributeMaxDynamicSharedMemorySize, GEMM_SMEM);
    cudaFuncSetAttribute(gemm_hmma<1>, cudaFuncAttributeMaxDynamicSharedMemorySize, GEMM_SMEM);
    cudaFuncSetAttribute(attn_mma, cudaFuncAttributeMaxDynamicSharedMemorySize, ATT_SMEM);

    // x -> fp16
    {
        int n4 = BT * TC / 4;
        conv_half<<<(n4 + 255) / 256, 256>>>((const float4*)x, (__half2*)xh, n4);
    }
    // weights -> fp16 transposed
    {
        dim3 gw(3 * TC / 32, TC / 32);
        conv_wt_half<<<gw, dim3(32, 8)>>>(Wa, wah, 3 * TC);
        dim3 gp(TC / 32, TC / 32);
        conv_wt_half<<<gp, dim3(32, 8)>>>(Wp, wph, TC);
    }
    // qkv GEMM with fused split-qkv epilogue (writes g_Qh/Ql/Kh/Kl/VTh/VTl)
    {
        dim3 g(3 * TC / BN, BT / BM);
        gemm_hmma<1><<<g, 512, GEMM_SMEM>>>(xh, wah, nullptr, 3 * TC);
    }
    // attention -> y fp16
    {
        dim3 ga(TT / 128, TH, TB);
        attn_mma<<<ga, 256, ATT_SMEM>>>(yh);
    }
    // out = y @ W_proj
    {
        dim3 g(TC / BN, BT / BM);
        gemm_hmma<0><<<g, 512, GEMM_SMEM>>>(yh, wph, out, TC);
    }
}